// round 1
// baseline (speedup 1.0000x reference)
#include <cuda_runtime.h>
#include <math.h>

// ---------------- problem dims ----------------
#define B_    2
#define NV_   975
#define TT    48
#define T2_   12
#define CC    128
#define VV    3
#define HH    8
#define DD    64
#define HDIM  512
#define LLAY  4
#define NB_   6
#define NHID_ 4
#define DIN_  387      // (C+1)*V
#define CY_   515      // HD + V
#define NVG   325      // NV/V
#define BNN   650      // B * NVG
#define MKV   (BNN*TT)   // 31200
#define MQ    (BNN*T2_)  // 7800
#define LOG2PI_F 1.8378770664093453f

// ---------------- scratch (device globals; no allocs allowed) ----------------
__device__ float g_ev[MKV*DIN_];            // [31200, 387]
__device__ float g_keys[LLAY*HH*MKV*DD];    // [(l*8+h), 31200, 64]
__device__ float g_vals[LLAY*HH*MKV*DD];
__device__ float g_attin[MQ*VV*CC];         // [7800, 384]
__device__ float g_attval[MQ*HDIM];         // [7800, 512]
__device__ float g_att[MQ*HDIM];
__device__ float g_h1[MQ*HDIM];
__device__ float g_h2[MQ*HDIM];
__device__ float g_inp[MQ*CY_];             // [7800, 515]
__device__ float g_s[MQ*VV];
__device__ float g_t[MQ*VV];
__device__ float g_u[MQ*VV];                // [bn, t2, v] -> row m=b*12+t2
__device__ float g_ld[MQ*VV];
__device__ float g_bnstats[T2_*VV*2];       // mean,var per (t2,v)

// ---------------- elementwise / setup kernels ----------------
__global__ void k_build_ev(const float* __restrict__ enc, const float* __restrict__ tv) {
    int idx = blockIdx.x * 256 + threadIdx.x;
    if (idx >= MKV * DIN_) return;
    int e  = idx % DIN_;
    int m  = idx / DIN_;
    int v  = e / (CC + 1);
    int cc = e % (CC + 1);
    int b  = m / TT;
    int tt = m % TT;
    int ob = b / NVG;
    int nv = (b % NVG) * VV + v;
    float val;
    if (cc < CC) val = enc[(((long)ob * NV_ + nv) * TT + tt) * CC + cc];
    else         val = tv[((long)ob * NV_ + nv) * TT + tt];
    g_ev[idx] = val;
}

__global__ void k_build_attin(const float* __restrict__ enc) {
    int idx = blockIdx.x * 256 + threadIdx.x;
    if (idx >= MQ * VV * CC) return;
    int col = idx % (VV * CC);
    int m   = idx / (VV * CC);
    int v   = col / CC;
    int cc  = col % CC;
    int b   = m / T2_;
    int q   = m % T2_;
    int ob  = b / NVG;
    int nv  = (b % NVG) * VV + v;
    g_attin[idx] = enc[(((long)ob * NV_ + nv) * TT + (TT - T2_) + q) * CC + cc];
}

__global__ void k_init_u(const float* __restrict__ tv) {
    int idx = blockIdx.x * 256 + threadIdx.x;
    if (idx >= MQ * VV) return;
    int v = idx % VV;
    int m = idx / VV;
    int b = m / T2_;
    int q = m % T2_;
    int ob = b / NVG;
    int nv = (b % NVG) * VV + v;
    g_u[idx]  = tv[((long)ob * NV_ + nv) * TT + (TT - T2_) + q];
    g_ld[idx] = 0.f;
}

__global__ void k_build_inp_y() {
    int idx = blockIdx.x * 256 + threadIdx.x;
    if (idx >= MQ * HDIM) return;
    int m = idx / HDIM;
    int c = idx % HDIM;
    g_inp[(long)m * CY_ + c] = g_attval[idx];
}

__global__ void k_write_mu(int blk) {
    int idx = blockIdx.x * 256 + threadIdx.x;
    if (idx >= MQ * VV) return;
    int v = idx % VV;
    int m = idx / VV;
    int mask = (v + blk) & 1;
    g_inp[(long)m * CY_ + HDIM + v] = mask ? g_u[idx] : 0.f;
}

__global__ void k_coupling(int blk) {
    int idx = blockIdx.x * 256 + threadIdx.x;
    if (idx >= MQ * VV) return;
    int v = idx % VV;
    int mask = (v + blk) & 1;
    if (!mask) {
        float s = g_s[idx];
        g_u[idx]  = (g_u[idx] - g_t[idx]) * expf(-s);
        g_ld[idx] -= s;
    }
}

__global__ void k_bn_stats() {
    int col = blockIdx.x;        // 0..35 = t2*3+v
    int tid = threadIdx.x;
    __shared__ float rs[256], rq[256];
    float s = 0.f, q = 0.f;
    for (int b = tid; b < BNN; b += 256) {
        float x = g_u[b * (T2_ * VV) + col];
        s += x; q += x * x;
    }
    rs[tid] = s; rq[tid] = q;
    __syncthreads();
    for (int st = 128; st > 0; st >>= 1) {
        if (tid < st) { rs[tid] += rs[tid + st]; rq[tid] += rq[tid + st]; }
        __syncthreads();
    }
    if (tid == 0) {
        float mean = rs[0] / (float)BNN;
        float var  = rq[0] / (float)BNN - mean * mean;
        g_bnstats[col * 2 + 0] = mean;
        g_bnstats[col * 2 + 1] = var;
    }
}

__global__ void k_bn_apply(const float* __restrict__ lgam, const float* __restrict__ beta) {
    int idx = blockIdx.x * 256 + threadIdx.x;
    if (idx >= MQ * VV) return;
    int col = idx % (T2_ * VV);
    int v   = col % VV;
    float mean = g_bnstats[col * 2 + 0];
    float var  = g_bnstats[col * 2 + 1];
    float lg = lgam[v], bt = beta[v];
    g_u[idx]  = expf(lg) * (g_u[idx] - mean) * rsqrtf(var + 1e-5f) + bt;
    g_ld[idx] += lg - 0.5f * logf(var + 1e-5f);
}

__global__ void k_final(float* __restrict__ out) {
    int b = blockIdx.x * 256 + threadIdx.x;
    if (b >= BNN) return;
    float acc = 0.f;
    for (int i = 0; i < T2_ * VV; i++) {
        float u = g_u[b * (T2_ * VV) + i];
        acc += 0.5f * u * u + 0.5f * LOG2PI_F - g_ld[b * (T2_ * VV) + i];
    }
    out[b] = acc;
}

// ---------------- generic tiled GEMM ----------------
// C[M,N] = actA(A[M,K]) @ B[K,N] + bias[N]   (all row-major)
// ACT applied to A elements on load: 0=none, 1=relu, 2=tanh
// batch via blockIdx.z with element strides sA,sB,sBias,sC.
template <int ACT>
__global__ void k_gemm(const float* __restrict__ A, const float* __restrict__ Bm,
                       const float* __restrict__ bias, float* __restrict__ C,
                       int M, int N, int K,
                       long sA, long sB, long sBias, long sC) {
    int bz = blockIdx.z;
    A    += (long)bz * sA;
    Bm   += (long)bz * sB;
    bias += (long)bz * sBias;
    C    += (long)bz * sC;

    __shared__ float As[16][65];
    __shared__ float Bs[16][64];

    int tile_m = blockIdx.y * 64;
    int tile_n = blockIdx.x * 64;
    int tx = threadIdx.x & 15;
    int ty = threadIdx.x >> 4;

    float acc[4][4];
#pragma unroll
    for (int i = 0; i < 4; i++)
#pragma unroll
        for (int j = 0; j < 4; j++) acc[i][j] = 0.f;

    for (int k0 = 0; k0 < K; k0 += 16) {
        // load A tile (coalesced over k), activation applied here
#pragma unroll
        for (int it = 0; it < 4; it++) {
            int i = threadIdx.x + it * 256;
            int mm = i >> 4, kk = i & 15;
            int gm = tile_m + mm, gk = k0 + kk;
            float a = 0.f;
            if (gm < M && gk < K) {
                a = A[(long)gm * K + gk];
                if (ACT == 1) a = fmaxf(a, 0.f);
                else if (ACT == 2) a = tanhf(a);
            }
            As[kk][mm] = a;
            // load B tile (coalesced over n)
            int kk2 = i >> 6, nn = i & 63;
            int gk2 = k0 + kk2, gn = tile_n + nn;
            Bs[kk2][nn] = (gk2 < K && gn < N) ? Bm[(long)gk2 * N + gn] : 0.f;
        }
        __syncthreads();
#pragma unroll
        for (int kk = 0; kk < 16; kk++) {
            float ar[4], br[4];
#pragma unroll
            for (int i = 0; i < 4; i++) ar[i] = As[kk][ty * 4 + i];
#pragma unroll
            for (int j = 0; j < 4; j++) br[j] = Bs[kk][tx * 4 + j];
#pragma unroll
            for (int i = 0; i < 4; i++)
#pragma unroll
                for (int j = 0; j < 4; j++) acc[i][j] += ar[i] * br[j];
        }
        __syncthreads();
    }

#pragma unroll
    for (int i = 0; i < 4; i++) {
        int row = tile_m + ty * 4 + i;
        if (row >= M) continue;
#pragma unroll
        for (int j = 0; j < 4; j++) {
            int col = tile_n + tx * 4 + j;
            if (col < N) C[(long)row * N + col] = acc[i][j] + bias[col];
        }
    }
}

// ---------------- fused attention: scores + mask + softmax + PV ----------------
// grid (T2, H, BN), 64 threads
__global__ void k_attn(const float* __restrict__ keys, const float* __restrict__ vals, int l) {
    int q = blockIdx.x, h = blockIdx.y, b = blockIdx.z;
    int tid = threadIdx.x;
    __shared__ float qv[64];
    __shared__ float pe[48];
    __shared__ float denom;

    qv[tid] = g_attval[((long)(b * T2_ + q)) * HDIM + h * DD + tid];
    __syncthreads();

    int lim = (TT - T2_) + q;  // valid keys: w < lim
    long base = ((long)(l * HH + h) * MKV + (long)b * TT) * DD;
    if (tid < TT) {
        float sc = -1e30f;
        if (tid < lim) {
            const float* kr = keys + base + (long)tid * DD;
            float dot = 0.f;
#pragma unroll
            for (int d = 0; d < DD; d++) dot += qv[d] * kr[d];
            sc = dot * 0.125f;   // D^-0.5
        }
        pe[tid] = sc;
    }
    __syncthreads();
    if (tid == 0) {
        float mx = -1e30f;
        for (int w = 0; w < lim; w++) mx = fmaxf(mx, pe[w]);
        float sm = 0.f;
        for (int w = 0; w < TT; w++) {
            float e = (w < lim) ? expf(pe[w] - mx) : 0.f;
            pe[w] = e; sm += e;
        }
        denom = sm;
    }
    __syncthreads();
    // output dim d = tid
    float acc = 0.f;
    const float* vb = vals + base + tid;
    for (int w = 0; w < lim; w++) acc += pe[w] * vb[(long)w * DD];
    g_att[((long)(b * T2_ + q)) * HDIM + h * DD + tid] = acc / denom;
}

// ---------------- add + layernorm (in place on x) ----------------
__global__ void k_add_ln(float* __restrict__ x, const float* __restrict__ y,
                         const float* __restrict__ gamma, const float* __restrict__ beta) {
    int m = blockIdx.x;
    int tid = threadIdx.x;
    long base = (long)m * HDIM;
    float v0 = x[base + tid] + y[base + tid];
    float v1 = x[base + 256 + tid] + y[base + 256 + tid];
    __shared__ float red[256];
    __shared__ float s_mean, s_rstd;
    red[tid] = v0 + v1;
    __syncthreads();
    for (int st = 128; st > 0; st >>= 1) {
        if (tid < st) red[tid] += red[tid + st];
        __syncthreads();
    }
    if (tid == 0) s_mean = red[0] / (float)HDIM;
    __syncthreads();
    float mn = s_mean;
    float d0 = v0 - mn, d1 = v1 - mn;
    red[tid] = d0 * d0 + d1 * d1;
    __syncthreads();
    for (int st = 128; st > 0; st >>= 1) {
        if (tid < st) red[tid] += red[tid + st];
        __syncthreads();
    }
    if (tid == 0) s_rstd = rsqrtf(red[0] / (float)HDIM + 1e-5f);
    __syncthreads();
    float r = s_rstd;
    x[base + tid]       = d0 * r * gamma[tid]       + beta[tid];
    x[base + 256 + tid] = d1 * r * gamma[256 + tid] + beta[256 + tid];
}

// ---------------- host orchestration ----------------
static inline int ceildiv(int a, int b) { return (a + b - 1) / b; }

extern "C" void kernel_launch(void* const* d_in, const int* in_sizes, int n_in,
                              void* d_out, int out_size) {
    const float* encoded   = (const float*)d_in[0];
    const float* true_val  = (const float*)d_in[1];
    const float* W_shift   = (const float*)d_in[2];
    const float* b_shift   = (const float*)d_in[3];
    const float* W_key     = (const float*)d_in[4];
    const float* b_key     = (const float*)d_in[5];
    const float* W_val     = (const float*)d_in[6];
    const float* b_val     = (const float*)d_in[7];
    const float* ln1_s     = (const float*)d_in[8];
    const float* ln1_b     = (const float*)d_in[9];
    const float* ff_w1     = (const float*)d_in[10];
    const float* ff_b1     = (const float*)d_in[11];
    const float* ff_w2     = (const float*)d_in[12];
    const float* ff_b2     = (const float*)d_in[13];
    const float* ln2_s     = (const float*)d_in[14];
    const float* ln2_b     = (const float*)d_in[15];
    const float* s_w_in    = (const float*)d_in[16];
    const float* s_b_in    = (const float*)d_in[17];
    const float* s_w_hid   = (const float*)d_in[18];
    const float* s_b_hid   = (const float*)d_in[19];
    const float* s_w_out   = (const float*)d_in[20];
    const float* s_b_out   = (const float*)d_in[21];
    const float* t_w_in    = (const float*)d_in[22];
    const float* t_b_in    = (const float*)d_in[23];
    const float* t_w_hid   = (const float*)d_in[24];
    const float* t_b_hid   = (const float*)d_in[25];
    const float* t_w_out   = (const float*)d_in[26];
    const float* t_b_out   = (const float*)d_in[27];
    const float* bn_lg     = (const float*)d_in[28];
    const float* bn_bt     = (const float*)d_in[29];

    float *ev, *keys, *vals, *attin, *attval, *att, *h1, *h2, *inp, *sbuf, *tbuf;
    cudaGetSymbolAddress((void**)&ev,     g_ev);
    cudaGetSymbolAddress((void**)&keys,   g_keys);
    cudaGetSymbolAddress((void**)&vals,   g_vals);
    cudaGetSymbolAddress((void**)&attin,  g_attin);
    cudaGetSymbolAddress((void**)&attval, g_attval);
    cudaGetSymbolAddress((void**)&att,    g_att);
    cudaGetSymbolAddress((void**)&h1,     g_h1);
    cudaGetSymbolAddress((void**)&h2,     g_h2);
    cudaGetSymbolAddress((void**)&inp,    g_inp);
    cudaGetSymbolAddress((void**)&sbuf,   g_s);
    cudaGetSymbolAddress((void**)&tbuf,   g_t);

    // 1) build ev and att_in
    k_build_ev<<<ceildiv(MKV * DIN_, 256), 256>>>(encoded, true_val);
    k_build_attin<<<ceildiv(MQ * VV * CC, 256), 256>>>(encoded);

    // 2) K/V projections: 32 batched GEMMs [31200,387]@[387,64]
    {
        dim3 g(1, ceildiv(MKV, 64), LLAY * HH);
        k_gemm<0><<<g, 256>>>(ev, W_key, b_key, keys, MKV, DD, DIN_,
                              0L, (long)DIN_ * DD, (long)DD, (long)MKV * DD);
        k_gemm<0><<<g, 256>>>(ev, W_val, b_val, vals, MKV, DD, DIN_,
                              0L, (long)DIN_ * DD, (long)DD, (long)MKV * DD);
    }

    // 3) att_value = att_in @ W_shift + b_shift   [7800,384]@[384,512]
    {
        dim3 g(ceildiv(HDIM, 64), ceildiv(MQ, 64), 1);
        k_gemm<0><<<g, 256>>>(attin, W_shift, b_shift, attval, MQ, HDIM, VV * CC,
                              0L, 0L, 0L, 0L);
    }

    // 4) transformer layers
    for (int l = 0; l < LLAY; l++) {
        k_attn<<<dim3(T2_, HH, BNN), 64>>>(keys, vals, l);
        k_add_ln<<<MQ, 256>>>(attval, att, ln1_s + (long)l * HDIM, ln1_b + (long)l * HDIM);
        dim3 g(ceildiv(HDIM, 64), ceildiv(MQ, 64), 1);
        k_gemm<0><<<g, 256>>>(attval, ff_w1 + (long)l * HDIM * HDIM, ff_b1 + (long)l * HDIM,
                              h1, MQ, HDIM, HDIM, 0L, 0L, 0L, 0L);
        k_gemm<1><<<g, 256>>>(h1, ff_w2 + (long)l * HDIM * HDIM, ff_b2 + (long)l * HDIM,
                              att, MQ, HDIM, HDIM, 0L, 0L, 0L, 0L);
        k_add_ln<<<MQ, 256>>>(attval, att, ln2_s + (long)l * HDIM, ln2_b + (long)l * HDIM);
    }

    // 5) RealNVP flow
    k_init_u<<<ceildiv(MQ * VV, 256), 256>>>(true_val);
    k_build_inp_y<<<ceildiv(MQ * HDIM, 256), 256>>>();

    dim3 gh(ceildiv(HDIM, 64), ceildiv(MQ, 64), 1);   // [7800, *, 512]
    dim3 go(1, ceildiv(MQ, 64), 1);                    // [7800, 3, 512]

    for (int blk = 0; blk < NB_; blk++) {
        k_write_mu<<<ceildiv(MQ * VV, 256), 256>>>(blk);

        // s-net (tanh)
        k_gemm<0><<<gh, 256>>>(inp, s_w_in + (long)blk * CY_ * HDIM, s_b_in + (long)blk * HDIM,
                               h1, MQ, HDIM, CY_, 0L, 0L, 0L, 0L);
        float* cur = h1; float* nxt = h2;
        for (int i = 0; i < NHID_; i++) {
            k_gemm<2><<<gh, 256>>>(cur,
                                   s_w_hid + ((long)blk * NHID_ + i) * HDIM * HDIM,
                                   s_b_hid + ((long)blk * NHID_ + i) * HDIM,
                                   nxt, MQ, HDIM, HDIM, 0L, 0L, 0L, 0L);
            float* tmp = cur; cur = nxt; nxt = tmp;
        }
        k_gemm<2><<<go, 256>>>(cur, s_w_out + (long)blk * HDIM * VV, s_b_out + (long)blk * VV,
                               sbuf, MQ, VV, HDIM, 0L, 0L, 0L, 0L);

        // t-net (relu)
        k_gemm<0><<<gh, 256>>>(inp, t_w_in + (long)blk * CY_ * HDIM, t_b_in + (long)blk * HDIM,
                               h1, MQ, HDIM, CY_, 0L, 0L, 0L, 0L);
        cur = h1; nxt = h2;
        for (int i = 0; i < NHID_; i++) {
            k_gemm<1><<<gh, 256>>>(cur,
                                   t_w_hid + ((long)blk * NHID_ + i) * HDIM * HDIM,
                                   t_b_hid + ((long)blk * NHID_ + i) * HDIM,
                                   nxt, MQ, HDIM, HDIM, 0L, 0L, 0L, 0L);
            float* tmp = cur; cur = nxt; nxt = tmp;
        }
        k_gemm<1><<<go, 256>>>(cur, t_w_out + (long)blk * HDIM * VV, t_b_out + (long)blk * VV,
                               tbuf, MQ, VV, HDIM, 0L, 0L, 0L, 0L);

        k_coupling<<<ceildiv(MQ * VV, 256), 256>>>(blk);
        k_bn_stats<<<T2_ * VV, 256>>>();
        k_bn_apply<<<ceildiv(MQ * VV, 256), 256>>>(bn_lg + (long)blk * VV, bn_bt + (long)blk * VV);
    }

    // 6) final NLL per bn row
    k_final<<<ceildiv(BNN, 256), 256>>>((float*)d_out);
}

// round 2
// speedup vs baseline: 1.0343x; 1.0343x over previous
#include <cuda_runtime.h>
#include <math.h>

// ---------------- problem dims ----------------
#define B_    2
#define NV_   975
#define TT    48
#define T2_   12
#define CC    128
#define VV    3
#define HH    8
#define DD    64
#define HDIM  512
#define LLAY  4
#define NB_   6
#define NHID_ 4
#define DIN_  387      // (C+1)*V
#define CY_   515      // HD + V
#define NVG   325      // NV/V
#define BNN   650      // B * NVG
#define MKV   (BNN*TT)   // 31200
#define MQ    (BNN*T2_)  // 7800
#define LOG2PI_F 1.8378770664093453f

// ---------------- scratch (device globals; no allocs allowed) ----------------
__device__ float g_ev[MKV*DIN_];            // [31200, 387]
__device__ float g_keys[LLAY*HH*MKV*DD];    // [(l*8+h), 31200, 64]
__device__ float g_vals[LLAY*HH*MKV*DD];
__device__ float g_attin[MQ*VV*CC];         // [7800, 384]
__device__ float g_attval[MQ*HDIM];         // [7800, 512]
__device__ float g_att[MQ*HDIM];
__device__ float g_h1[MQ*HDIM];
__device__ float g_h2[MQ*HDIM];
__device__ float g_inp[MQ*CY_];             // [7800, 515]
__device__ float g_s[MQ*VV];
__device__ float g_t[MQ*VV];
__device__ float g_u[MQ*VV];
__device__ float g_ld[MQ*VV];
__device__ float g_bnstats[T2_*VV*2];

// ---------------- elementwise / setup kernels ----------------
__global__ void k_build_ev(const float* __restrict__ enc, const float* __restrict__ tv) {
    int idx = blockIdx.x * 256 + threadIdx.x;
    if (idx >= MKV * DIN_) return;
    int e  = idx % DIN_;
    int m  = idx / DIN_;
    int v  = e / (CC + 1);
    int cc = e % (CC + 1);
    int b  = m / TT;
    int tt = m % TT;
    int ob = b / NVG;
    int nv = (b % NVG) * VV + v;
    float val;
    if (cc < CC) val = enc[(((long)ob * NV_ + nv) * TT + tt) * CC + cc];
    else         val = tv[((long)ob * NV_ + nv) * TT + tt];
    g_ev[idx] = val;
}

__global__ void k_build_attin(const float* __restrict__ enc) {
    int idx = blockIdx.x * 256 + threadIdx.x;
    if (idx >= MQ * VV * CC) return;
    int col = idx % (VV * CC);
    int m   = idx / (VV * CC);
    int v   = col / CC;
    int cc  = col % CC;
    int b   = m / T2_;
    int q   = m % T2_;
    int ob  = b / NVG;
    int nv  = (b % NVG) * VV + v;
    g_attin[idx] = enc[(((long)ob * NV_ + nv) * TT + (TT - T2_) + q) * CC + cc];
}

__global__ void k_init_u(const float* __restrict__ tv) {
    int idx = blockIdx.x * 256 + threadIdx.x;
    if (idx >= MQ * VV) return;
    int v = idx % VV;
    int m = idx / VV;
    int b = m / T2_;
    int q = m % T2_;
    int ob = b / NVG;
    int nv = (b % NVG) * VV + v;
    g_u[idx]  = tv[((long)ob * NV_ + nv) * TT + (TT - T2_) + q];
    g_ld[idx] = 0.f;
}

__global__ void k_build_inp_y() {
    int idx = blockIdx.x * 256 + threadIdx.x;
    if (idx >= MQ * HDIM) return;
    int m = idx / HDIM;
    int c = idx % HDIM;
    g_inp[(long)m * CY_ + c] = g_attval[idx];
}

__global__ void k_write_mu(int blk) {
    int idx = blockIdx.x * 256 + threadIdx.x;
    if (idx >= MQ * VV) return;
    int v = idx % VV;
    int m = idx / VV;
    int mask = (v + blk) & 1;
    g_inp[(long)m * CY_ + HDIM + v] = mask ? g_u[idx] : 0.f;
}

__global__ void k_coupling(int blk) {
    int idx = blockIdx.x * 256 + threadIdx.x;
    if (idx >= MQ * VV) return;
    int v = idx % VV;
    int mask = (v + blk) & 1;
    if (!mask) {
        float s = g_s[idx];
        g_u[idx]  = (g_u[idx] - g_t[idx]) * expf(-s);
        g_ld[idx] -= s;
    }
}

__global__ void k_bn_stats() {
    int col = blockIdx.x;
    int tid = threadIdx.x;
    __shared__ float rs[256], rq[256];
    float s = 0.f, q = 0.f;
    for (int b = tid; b < BNN; b += 256) {
        float x = g_u[b * (T2_ * VV) + col];
        s += x; q += x * x;
    }
    rs[tid] = s; rq[tid] = q;
    __syncthreads();
    for (int st = 128; st > 0; st >>= 1) {
        if (tid < st) { rs[tid] += rs[tid + st]; rq[tid] += rq[tid + st]; }
        __syncthreads();
    }
    if (tid == 0) {
        float mean = rs[0] / (float)BNN;
        float var  = rq[0] / (float)BNN - mean * mean;
        g_bnstats[col * 2 + 0] = mean;
        g_bnstats[col * 2 + 1] = var;
    }
}

__global__ void k_bn_apply(const float* __restrict__ lgam, const float* __restrict__ beta) {
    int idx = blockIdx.x * 256 + threadIdx.x;
    if (idx >= MQ * VV) return;
    int col = idx % (T2_ * VV);
    int v   = col % VV;
    float mean = g_bnstats[col * 2 + 0];
    float var  = g_bnstats[col * 2 + 1];
    float lg = lgam[v], bt = beta[v];
    g_u[idx]  = expf(lg) * (g_u[idx] - mean) * rsqrtf(var + 1e-5f) + bt;
    g_ld[idx] += lg - 0.5f * logf(var + 1e-5f);
}

__global__ void k_final(float* __restrict__ out) {
    int b = blockIdx.x * 256 + threadIdx.x;
    if (b >= BNN) return;
    float acc = 0.f;
    for (int i = 0; i < T2_ * VV; i++) {
        float u = g_u[b * (T2_ * VV) + i];
        acc += 0.5f * u * u + 0.5f * LOG2PI_F - g_ld[b * (T2_ * VV) + i];
    }
    out[b] = acc;
}

// ---------------- tf32x3 tensor-core GEMM ----------------
// C[M,N] = actA(A[M,K]) @ B[K,N] + bias[N], fp32-class accuracy via hi/lo tf32 split.
// Block tile 128x64, BK=16, 256 threads (8 warps, each 32x32 via 2x4 m16n8k8).
#define BMt 128
#define BNt 64
#define BKt 16
#define BMP 136   // pad: 136%32==8 -> (8*tig+grp) conflict-free fragment lds
#define BNP 72    // pad: 72%32==8

__device__ __forceinline__ unsigned f2tf(float x) {
    unsigned r;
    asm("cvt.rna.tf32.f32 %0, %1;" : "=r"(r) : "f"(x));
    return r;
}

__device__ __forceinline__ void mma8(float* c, const unsigned* a, const unsigned* b) {
    asm volatile(
        "mma.sync.aligned.m16n8k8.row.col.f32.tf32.tf32.f32 "
        "{%0,%1,%2,%3}, {%4,%5,%6,%7}, {%8,%9}, {%0,%1,%2,%3};"
        : "+f"(c[0]), "+f"(c[1]), "+f"(c[2]), "+f"(c[3])
        : "r"(a[0]), "r"(a[1]), "r"(a[2]), "r"(a[3]), "r"(b[0]), "r"(b[1]));
}

template <int ACT>
__global__ void k_mma(const float* __restrict__ A, const float* __restrict__ Bm,
                      const float* __restrict__ bias, float* __restrict__ C,
                      int M, int N, int K,
                      long sA, long sB, long sBias, long sC) {
    __shared__ float As[BKt][BMP];
    __shared__ float Bs[BKt][BNP];

    int bz = blockIdx.z;
    A    += (long)bz * sA;
    Bm   += (long)bz * sB;
    bias += (long)bz * sBias;
    C    += (long)bz * sC;

    int tile_m = blockIdx.y * BMt;
    int tile_n = blockIdx.x * BNt;
    int tid  = threadIdx.x;
    int lane = tid & 31, w = tid >> 5;
    int grp = lane >> 2, tig = lane & 3;
    int wm = w & 3, wn = w >> 2;   // 4 warps along M, 2 along N

    float acc[2][4][4];
#pragma unroll
    for (int i = 0; i < 2; i++)
#pragma unroll
        for (int j = 0; j < 4; j++)
#pragma unroll
            for (int e = 0; e < 4; e++) acc[i][j][e] = 0.f;

    for (int k0 = 0; k0 < K; k0 += BKt) {
        // load A tile [128 x 16] (coalesced over k), activation applied here
#pragma unroll
        for (int it = 0; it < 8; it++) {
            int i = tid + it * 256;
            int mm = i >> 4, kk = i & 15;
            int gm = tile_m + mm, gk = k0 + kk;
            float a = 0.f;
            if (gm < M && gk < K) {
                a = A[(long)gm * K + gk];
                if (ACT == 1) a = fmaxf(a, 0.f);
                else if (ACT == 2) a = tanhf(a);
            }
            As[kk][mm] = a;
        }
        // load B tile [16 x 64] (coalesced over n)
#pragma unroll
        for (int it = 0; it < 4; it++) {
            int i = tid + it * 256;
            int kk = i >> 6, nn = i & 63;
            int gk = k0 + kk, gn = tile_n + nn;
            Bs[kk][nn] = (gk < K && gn < N) ? Bm[(long)gk * N + gn] : 0.f;
        }
        __syncthreads();

#pragma unroll
        for (int ks = 0; ks < BKt; ks += 8) {
            unsigned ah[2][4], al[2][4], bh[4][2], bl[4][2];
#pragma unroll
            for (int i = 0; i < 2; i++) {
                int rb = wm * 32 + i * 16 + grp;
                float x0 = As[ks + tig][rb];
                float x1 = As[ks + tig][rb + 8];
                float x2 = As[ks + tig + 4][rb];
                float x3 = As[ks + tig + 4][rb + 8];
                ah[i][0] = f2tf(x0); al[i][0] = f2tf(x0 - __uint_as_float(ah[i][0]));
                ah[i][1] = f2tf(x1); al[i][1] = f2tf(x1 - __uint_as_float(ah[i][1]));
                ah[i][2] = f2tf(x2); al[i][2] = f2tf(x2 - __uint_as_float(ah[i][2]));
                ah[i][3] = f2tf(x3); al[i][3] = f2tf(x3 - __uint_as_float(ah[i][3]));
            }
#pragma unroll
            for (int j = 0; j < 4; j++) {
                int nb = wn * 32 + j * 8 + grp;
                float y0 = Bs[ks + tig][nb];
                float y1 = Bs[ks + tig + 4][nb];
                bh[j][0] = f2tf(y0); bl[j][0] = f2tf(y0 - __uint_as_float(bh[j][0]));
                bh[j][1] = f2tf(y1); bl[j][1] = f2tf(y1 - __uint_as_float(bh[j][1]));
            }
#pragma unroll
            for (int i = 0; i < 2; i++)
#pragma unroll
                for (int j = 0; j < 4; j++) {
                    mma8(acc[i][j], ah[i], bh[j]);
                    mma8(acc[i][j], al[i], bh[j]);
                    mma8(acc[i][j], ah[i], bl[j]);
                }
        }
        __syncthreads();
    }

    // epilogue: D = acc + bias
#pragma unroll
    for (int i = 0; i < 2; i++) {
        int row0 = tile_m + wm * 32 + i * 16 + grp;
        int row1 = row0 + 8;
#pragma unroll
        for (int j = 0; j < 4; j++) {
            int col = tile_n + wn * 32 + j * 8 + tig * 2;
            if (col < N) {
                float bsv0 = bias[col], bsv1 = bias[col + 1];
                if (row0 < M) {
                    C[(long)row0 * N + col]     = acc[i][j][0] + bsv0;
                    C[(long)row0 * N + col + 1] = acc[i][j][1] + bsv1;
                }
                if (row1 < M) {
                    C[(long)row1 * N + col]     = acc[i][j][2] + bsv0;
                    C[(long)row1 * N + col + 1] = acc[i][j][3] + bsv1;
                }
            }
        }
    }
}

// ---------------- SIMT GEMM (kept for tiny N=3 output layers) ----------------
template <int ACT>
__global__ void k_gemm(const float* __restrict__ A, const float* __restrict__ Bm,
                       const float* __restrict__ bias, float* __restrict__ C,
                       int M, int N, int K,
                       long sA, long sB, long sBias, long sC) {
    int bz = blockIdx.z;
    A    += (long)bz * sA;
    Bm   += (long)bz * sB;
    bias += (long)bz * sBias;
    C    += (long)bz * sC;

    __shared__ float As[16][65];
    __shared__ float Bs[16][64];

    int tile_m = blockIdx.y * 64;
    int tile_n = blockIdx.x * 64;
    int tx = threadIdx.x & 15;
    int ty = threadIdx.x >> 4;

    float acc[4][4];
#pragma unroll
    for (int i = 0; i < 4; i++)
#pragma unroll
        for (int j = 0; j < 4; j++) acc[i][j] = 0.f;

    for (int k0 = 0; k0 < K; k0 += 16) {
#pragma unroll
        for (int it = 0; it < 4; it++) {
            int i = threadIdx.x + it * 256;
            int mm = i >> 4, kk = i & 15;
            int gm = tile_m + mm, gk = k0 + kk;
            float a = 0.f;
            if (gm < M && gk < K) {
                a = A[(long)gm * K + gk];
                if (ACT == 1) a = fmaxf(a, 0.f);
                else if (ACT == 2) a = tanhf(a);
            }
            As[kk][mm] = a;
            int kk2 = i >> 6, nn = i & 63;
            int gk2 = k0 + kk2, gn = tile_n + nn;
            Bs[kk2][nn] = (gk2 < K && gn < N) ? Bm[(long)gk2 * N + gn] : 0.f;
        }
        __syncthreads();
#pragma unroll
        for (int kk = 0; kk < 16; kk++) {
            float ar[4], br[4];
#pragma unroll
            for (int i = 0; i < 4; i++) ar[i] = As[kk][ty * 4 + i];
#pragma unroll
            for (int j = 0; j < 4; j++) br[j] = Bs[kk][tx * 4 + j];
#pragma unroll
            for (int i = 0; i < 4; i++)
#pragma unroll
                for (int j = 0; j < 4; j++) acc[i][j] += ar[i] * br[j];
        }
        __syncthreads();
    }

#pragma unroll
    for (int i = 0; i < 4; i++) {
        int row = tile_m + ty * 4 + i;
        if (row >= M) continue;
#pragma unroll
        for (int j = 0; j < 4; j++) {
            int col = tile_n + tx * 4 + j;
            if (col < N) C[(long)row * N + col] = acc[i][j] + bias[col];
        }
    }
}

// ---------------- fused attention ----------------
__global__ void k_attn(const float* __restrict__ keys, const float* __restrict__ vals, int l) {
    int q = blockIdx.x, h = blockIdx.y, b = blockIdx.z;
    int tid = threadIdx.x;
    __shared__ float qv[64];
    __shared__ float pe[48];
    __shared__ float denom;

    qv[tid] = g_attval[((long)(b * T2_ + q)) * HDIM + h * DD + tid];
    __syncthreads();

    int lim = (TT - T2_) + q;
    long base = ((long)(l * HH + h) * MKV + (long)b * TT) * DD;
    if (tid < TT) {
        float sc = -1e30f;
        if (tid < lim) {
            const float* kr = keys + base + (long)tid * DD;
            float dot = 0.f;
#pragma unroll
            for (int d = 0; d < DD; d++) dot += qv[d] * kr[d];
            sc = dot * 0.125f;
        }
        pe[tid] = sc;
    }
    __syncthreads();
    if (tid == 0) {
        float mx = -1e30f;
        for (int w = 0; w < lim; w++) mx = fmaxf(mx, pe[w]);
        float sm = 0.f;
        for (int w = 0; w < TT; w++) {
            float e = (w < lim) ? expf(pe[w] - mx) : 0.f;
            pe[w] = e; sm += e;
        }
        denom = sm;
    }
    __syncthreads();
    float acc = 0.f;
    const float* vb = vals + base + tid;
    for (int w = 0; w < lim; w++) acc += pe[w] * vb[(long)w * DD];
    g_att[((long)(b * T2_ + q)) * HDIM + h * DD + tid] = acc / denom;
}

// ---------------- add + layernorm ----------------
__global__ void k_add_ln(float* __restrict__ x, const float* __restrict__ y,
                         const float* __restrict__ gamma, const float* __restrict__ beta) {
    int m = blockIdx.x;
    int tid = threadIdx.x;
    long base = (long)m * HDIM;
    float v0 = x[base + tid] + y[base + tid];
    float v1 = x[base + 256 + tid] + y[base + 256 + tid];
    __shared__ float red[256];
    __shared__ float s_mean, s_rstd;
    red[tid] = v0 + v1;
    __syncthreads();
    for (int st = 128; st > 0; st >>= 1) {
        if (tid < st) red[tid] += red[tid + st];
        __syncthreads();
    }
    if (tid == 0) s_mean = red[0] / (float)HDIM;
    __syncthreads();
    float mn = s_mean;
    float d0 = v0 - mn, d1 = v1 - mn;
    red[tid] = d0 * d0 + d1 * d1;
    __syncthreads();
    for (int st = 128; st > 0; st >>= 1) {
        if (tid < st) red[tid] += red[tid + st];
        __syncthreads();
    }
    if (tid == 0) s_rstd = rsqrtf(red[0] / (float)HDIM + 1e-5f);
    __syncthreads();
    float r = s_rstd;
    x[base + tid]       = d0 * r * gamma[tid]       + beta[tid];
    x[base + 256 + tid] = d1 * r * gamma[256 + tid] + beta[256 + tid];
}

// ---------------- host orchestration ----------------
static inline int ceildiv(int a, int b) { return (a + b - 1) / b; }

extern "C" void kernel_launch(void* const* d_in, const int* in_sizes, int n_in,
                              void* d_out, int out_size) {
    const float* encoded   = (const float*)d_in[0];
    const float* true_val  = (const float*)d_in[1];
    const float* W_shift   = (const float*)d_in[2];
    const float* b_shift   = (const float*)d_in[3];
    const float* W_key     = (const float*)d_in[4];
    const float* b_key     = (const float*)d_in[5];
    const float* W_val     = (const float*)d_in[6];
    const float* b_val     = (const float*)d_in[7];
    const float* ln1_s     = (const float*)d_in[8];
    const float* ln1_b     = (const float*)d_in[9];
    const float* ff_w1     = (const float*)d_in[10];
    const float* ff_b1     = (const float*)d_in[11];
    const float* ff_w2     = (const float*)d_in[12];
    const float* ff_b2     = (const float*)d_in[13];
    const float* ln2_s     = (const float*)d_in[14];
    const float* ln2_b     = (const float*)d_in[15];
    const float* s_w_in    = (const float*)d_in[16];
    const float* s_b_in    = (const float*)d_in[17];
    const float* s_w_hid   = (const float*)d_in[18];
    const float* s_b_hid   = (const float*)d_in[19];
    const float* s_w_out   = (const float*)d_in[20];
    const float* s_b_out   = (const float*)d_in[21];
    const float* t_w_in    = (const float*)d_in[22];
    const float* t_b_in    = (const float*)d_in[23];
    const float* t_w_hid   = (const float*)d_in[24];
    const float* t_b_hid   = (const float*)d_in[25];
    const float* t_w_out   = (const float*)d_in[26];
    const float* t_b_out   = (const float*)d_in[27];
    const float* bn_lg     = (const float*)d_in[28];
    const float* bn_bt     = (const float*)d_in[29];

    float *ev, *keys, *vals, *attin, *attval, *att, *h1, *h2, *inp, *sbuf, *tbuf;
    cudaGetSymbolAddress((void**)&ev,     g_ev);
    cudaGetSymbolAddress((void**)&keys,   g_keys);
    cudaGetSymbolAddress((void**)&vals,   g_vals);
    cudaGetSymbolAddress((void**)&attin,  g_attin);
    cudaGetSymbolAddress((void**)&attval, g_attval);
    cudaGetSymbolAddress((void**)&att,    g_att);
    cudaGetSymbolAddress((void**)&h1,     g_h1);
    cudaGetSymbolAddress((void**)&h2,     g_h2);
    cudaGetSymbolAddress((void**)&inp,    g_inp);
    cudaGetSymbolAddress((void**)&sbuf,   g_s);
    cudaGetSymbolAddress((void**)&tbuf,   g_t);

    // 1) build ev and att_in
    k_build_ev<<<ceildiv(MKV * DIN_, 256), 256>>>(encoded, true_val);
    k_build_attin<<<ceildiv(MQ * VV * CC, 256), 256>>>(encoded);

    // 2) K/V projections: 32 batched GEMMs [31200,387]@[387,64] on tensor cores
    {
        dim3 g(1, ceildiv(MKV, BMt), LLAY * HH);
        k_mma<0><<<g, 256>>>(ev, W_key, b_key, keys, MKV, DD, DIN_,
                             0L, (long)DIN_ * DD, (long)DD, (long)MKV * DD);
        k_mma<0><<<g, 256>>>(ev, W_val, b_val, vals, MKV, DD, DIN_,
                             0L, (long)DIN_ * DD, (long)DD, (long)MKV * DD);
    }

    // 3) att_value = att_in @ W_shift + b_shift
    {
        dim3 g(HDIM / BNt, ceildiv(MQ, BMt), 1);
        k_mma<0><<<g, 256>>>(attin, W_shift, b_shift, attval, MQ, HDIM, VV * CC,
                             0L, 0L, 0L, 0L);
    }

    // 4) transformer layers
    for (int l = 0; l < LLAY; l++) {
        k_attn<<<dim3(T2_, HH, BNN), 64>>>(keys, vals, l);
        k_add_ln<<<MQ, 256>>>(attval, att, ln1_s + (long)l * HDIM, ln1_b + (long)l * HDIM);
        dim3 g(HDIM / BNt, ceildiv(MQ, BMt), 1);
        k_mma<0><<<g, 256>>>(attval, ff_w1 + (long)l * HDIM * HDIM, ff_b1 + (long)l * HDIM,
                             h1, MQ, HDIM, HDIM, 0L, 0L, 0L, 0L);
        k_mma<1><<<g, 256>>>(h1, ff_w2 + (long)l * HDIM * HDIM, ff_b2 + (long)l * HDIM,
                             att, MQ, HDIM, HDIM, 0L, 0L, 0L, 0L);
        k_add_ln<<<MQ, 256>>>(attval, att, ln2_s + (long)l * HDIM, ln2_b + (long)l * HDIM);
    }

    // 5) RealNVP flow
    k_init_u<<<ceildiv(MQ * VV, 256), 256>>>(true_val);
    k_build_inp_y<<<ceildiv(MQ * HDIM, 256), 256>>>();

    dim3 gh(HDIM / BNt, ceildiv(MQ, BMt), 1);   // tensor-core [7800,*,512]
    dim3 go(1, ceildiv(MQ, 64), 1);             // SIMT [7800,3,512]

    for (int blk = 0; blk < NB_; blk++) {
        k_write_mu<<<ceildiv(MQ * VV, 256), 256>>>(blk);

        // s-net (tanh)
        k_mma<0><<<gh, 256>>>(inp, s_w_in + (long)blk * CY_ * HDIM, s_b_in + (long)blk * HDIM,
                              h1, MQ, HDIM, CY_, 0L, 0L, 0L, 0L);
        float* cur = h1; float* nxt = h2;
        for (int i = 0; i < NHID_; i++) {
            k_mma<2><<<gh, 256>>>(cur,
                                  s_w_hid + ((long)blk * NHID_ + i) * HDIM * HDIM,
                                  s_b_hid + ((long)blk * NHID_ + i) * HDIM,
                                  nxt, MQ, HDIM, HDIM, 0L, 0L, 0L, 0L);
            float* tmp = cur; cur = nxt; nxt = tmp;
        }
        k_gemm<2><<<go, 256>>>(cur, s_w_out + (long)blk * HDIM * VV, s_b_out + (long)blk * VV,
                               sbuf, MQ, VV, HDIM, 0L, 0L, 0L, 0L);

        // t-net (relu)
        k_mma<0><<<gh, 256>>>(inp, t_w_in + (long)blk * CY_ * HDIM, t_b_in + (long)blk * HDIM,
                              h1, MQ, HDIM, CY_, 0L, 0L, 0L, 0L);
        cur = h1; nxt = h2;
        for (int i = 0; i < NHID_; i++) {
            k_mma<1><<<gh, 256>>>(cur,
                                  t_w_hid + ((long)blk * NHID_ + i) * HDIM * HDIM,
                                  t_b_hid + ((long)blk * NHID_ + i) * HDIM,
                                  nxt, MQ, HDIM, HDIM, 0L, 0L, 0L, 0L);
            float* tmp = cur; cur = nxt; nxt = tmp;
        }
        k_gemm<1><<<go, 256>>>(cur, t_w_out + (long)blk * HDIM * VV, t_b_out + (long)blk * VV,
                               tbuf, MQ, VV, HDIM, 0L, 0L, 0L, 0L);

        k_coupling<<<ceildiv(MQ * VV, 256), 256>>>(blk);
        k_bn_stats<<<T2_ * VV, 256>>>();
        k_bn_apply<<<ceildiv(MQ * VV, 256), 256>>>(bn_lg + (long)blk * VV, bn_bt + (long)blk * VV);
    }

    // 6) final NLL per bn row
    k_final<<<ceildiv(BNN, 256), 256>>>((float*)d_out);
}

// round 3
// speedup vs baseline: 1.3216x; 1.2777x over previous
#include <cuda_runtime.h>
#include <cuda_bf16.h>
#include <math.h>

// ---------------- problem dims ----------------
#define B_    2
#define NV_   975
#define TT    48
#define T2_   12
#define CC    128
#define VV    3
#define HH    8
#define DD    64
#define HDIM  512
#define LLAY  4
#define NB_   6
#define NHID_ 4
#define DIN_  387
#define CY_   515
#define NVG   325
#define BNN   650
#define MKV   (BNN*TT)   // 31200
#define MQ    (BNN*T2_)  // 7800
#define LOG2PI_F 1.8378770664093453f

// ---------------- scratch ----------------
__device__ float g_ev[MKV*DIN_];
__device__ float g_keys[LLAY*HH*MKV*DD];
__device__ float g_vals[LLAY*HH*MKV*DD];
__device__ float g_attin[MQ*VV*CC];
__device__ float g_attval[MQ*HDIM];
__device__ float g_att[MQ*HDIM];
__device__ float g_h1[MQ*HDIM];   // s ping
__device__ float g_h2[MQ*HDIM];   // s pong
__device__ float g_h3[MQ*HDIM];   // t ping
__device__ float g_h4[MQ*HDIM];   // t pong
__device__ float g_inp[MQ*CY_];
__device__ float g_s[MQ*VV];
__device__ float g_t[MQ*VV];
__device__ float g_u[MQ*VV];
__device__ float g_ld[MQ*VV];
__device__ float g_bnstats[T2_*VV*2];

// ---------------- setup kernels ----------------
__global__ void k_build_ev(const float* __restrict__ enc, const float* __restrict__ tv) {
    int idx = blockIdx.x * 256 + threadIdx.x;
    if (idx >= MKV * DIN_) return;
    int e  = idx % DIN_;
    int m  = idx / DIN_;
    int v  = e / (CC + 1);
    int cc = e % (CC + 1);
    int b  = m / TT;
    int tt = m % TT;
    int ob = b / NVG;
    int nv = (b % NVG) * VV + v;
    float val;
    if (cc < CC) val = enc[(((long)ob * NV_ + nv) * TT + tt) * CC + cc];
    else         val = tv[((long)ob * NV_ + nv) * TT + tt];
    g_ev[idx] = val;
}

__global__ void k_build_attin(const float* __restrict__ enc) {
    int idx = blockIdx.x * 256 + threadIdx.x;
    if (idx >= MQ * VV * CC) return;
    int col = idx % (VV * CC);
    int m   = idx / (VV * CC);
    int v   = col / CC;
    int cc  = col % CC;
    int b   = m / T2_;
    int q   = m % T2_;
    int ob  = b / NVG;
    int nv  = (b % NVG) * VV + v;
    g_attin[idx] = enc[(((long)ob * NV_ + nv) * TT + (TT - T2_) + q) * CC + cc];
}

// init u/ld and write mask-mu for flow block 0
__global__ void k_init_u_mu(const float* __restrict__ tv) {
    int idx = blockIdx.x * 256 + threadIdx.x;
    if (idx >= MQ * VV) return;
    int v = idx % VV;
    int m = idx / VV;
    int b = m / T2_;
    int q = m % T2_;
    int ob = b / NVG;
    int nv = (b % NVG) * VV + v;
    float u = tv[((long)ob * NV_ + nv) * TT + (TT - T2_) + q];
    g_u[idx]  = u;
    g_ld[idx] = 0.f;
    int mask = v & 1;   // blk = 0
    g_inp[(long)m * CY_ + HDIM + v] = mask ? u : 0.f;
}

__global__ void k_build_inp_y() {
    int idx = blockIdx.x * 256 + threadIdx.x;
    if (idx >= MQ * HDIM) return;
    int m = idx / HDIM;
    int c = idx % HDIM;
    g_inp[(long)m * CY_ + c] = g_attval[idx];
}

// coupling transform fused with batch-norm statistics (block per (t2,v) column)
__global__ void k_coupling_stats(int blk) {
    int col = blockIdx.x;          // 0..35
    int v   = col % VV;
    int mask = (v + blk) & 1;
    int tid = threadIdx.x;
    __shared__ float rs[256], rq[256];
    float s = 0.f, q = 0.f;
    for (int b = tid; b < BNN; b += 256) {
        int e = b * (T2_ * VV) + col;
        float u = g_u[e];
        if (!mask) {
            float sv = g_s[e];
            u = (u - g_t[e]) * expf(-sv);
            g_u[e] = u;
            g_ld[e] -= sv;
        }
        s += u; q += u * u;
    }
    rs[tid] = s; rq[tid] = q;
    __syncthreads();
    for (int st = 128; st > 0; st >>= 1) {
        if (tid < st) { rs[tid] += rs[tid + st]; rq[tid] += rq[tid + st]; }
        __syncthreads();
    }
    if (tid == 0) {
        float mean = rs[0] / (float)BNN;
        float var  = rq[0] / (float)BNN - mean * mean;
        g_bnstats[col * 2 + 0] = mean;
        g_bnstats[col * 2 + 1] = var;
    }
}

// BN apply fused with next block's masked-mu write
__global__ void k_bn_apply_mu(const float* __restrict__ lgam, const float* __restrict__ beta, int blk) {
    int idx = blockIdx.x * 256 + threadIdx.x;
    if (idx >= MQ * VV) return;
    int col = idx % (T2_ * VV);
    int v   = col % VV;
    float mean = g_bnstats[col * 2 + 0];
    float var  = g_bnstats[col * 2 + 1];
    float lg = lgam[v], bt = beta[v];
    float u = expf(lg) * (g_u[idx] - mean) * rsqrtf(var + 1e-5f) + bt;
    g_u[idx]  = u;
    g_ld[idx] += lg - 0.5f * logf(var + 1e-5f);
    if (blk < NB_ - 1) {
        int nmask = (v + blk + 1) & 1;
        int m = idx / VV;
        g_inp[(long)m * CY_ + HDIM + v] = nmask ? u : 0.f;
    }
}

__global__ void k_final(float* __restrict__ out) {
    int b = blockIdx.x * 256 + threadIdx.x;
    if (b >= BNN) return;
    float acc = 0.f;
    for (int i = 0; i < T2_ * VV; i++) {
        float u = g_u[b * (T2_ * VV) + i];
        acc += 0.5f * u * u + 0.5f * LOG2PI_F - g_ld[b * (T2_ * VV) + i];
    }
    out[b] = acc;
}

// ---------------- bf16x3 tensor-core GEMM (dual-set via blockIdx.z) ----------------
// C = A @ W + bias, fp32-class accuracy: a = ah + al (bf16 each), 3 mma terms.
// Block tile 128x64, BK=32, 256 threads, 8 warps of 32x32 (2x4 m16n8k16 frags).
// Epilogue activation ACTOUT: 0 none, 1 relu, 2 tanh (stored post-act).
#define BM 128
#define BN 64
#define BK 32
#define KP 16      // k-pairs per tile
#define AP 136     // A smem pitch (mod 32 == 8 -> conflict-free frag LDS)
#define BP 72

__device__ __forceinline__ unsigned splitpack(float x0, float x1, unsigned& lo) {
    __nv_bfloat16 h0 = __float2bfloat16_rn(x0);
    __nv_bfloat16 h1 = __float2bfloat16_rn(x1);
    float r0 = x0 - __bfloat162float(h0);
    float r1 = x1 - __bfloat162float(h1);
    __nv_bfloat162 hp = __halves2bfloat162(h0, h1);
    __nv_bfloat162 lp = __halves2bfloat162(__float2bfloat16_rn(r0), __float2bfloat16_rn(r1));
    lo = *reinterpret_cast<unsigned*>(&lp);
    return *reinterpret_cast<unsigned*>(&hp);
}

__device__ __forceinline__ void mma16(float* c, const unsigned* a, const unsigned* b) {
    asm volatile(
        "mma.sync.aligned.m16n8k16.row.col.f32.bf16.bf16.f32 "
        "{%0,%1,%2,%3}, {%4,%5,%6,%7}, {%8,%9}, {%0,%1,%2,%3};"
        : "+f"(c[0]), "+f"(c[1]), "+f"(c[2]), "+f"(c[3])
        : "r"(a[0]), "r"(a[1]), "r"(a[2]), "r"(a[3]), "r"(b[0]), "r"(b[1]));
}

template <int ACTOUT0, int ACTOUT1>
__global__ void __launch_bounds__(256)
k_mma2(const float* __restrict__ A0, const float* __restrict__ W0,
       const float* __restrict__ bias0, float* __restrict__ C0,
       const float* __restrict__ A1, const float* __restrict__ W1,
       const float* __restrict__ bias1, float* __restrict__ C1,
       int M, int N, int K, int z0,
       long sA, long sW, long sb, long sC) {
    __shared__ unsigned Ah[KP][AP], Al[KP][AP], Bh[KP][BP], Bl[KP][BP];

    bool first = ((int)blockIdx.z < z0);
    int zl = first ? blockIdx.z : blockIdx.z - z0;
    const float* A    = (first ? A0 : A1) + (long)zl * sA;
    const float* W    = (first ? W0 : W1) + (long)zl * sW;
    const float* bias = (first ? bias0 : bias1) + (long)zl * sb;
    float* C          = (first ? C0 : C1) + (long)zl * sC;

    int tile_m = blockIdx.y * BM;
    int tile_n = blockIdx.x * BN;
    int tid = threadIdx.x, lane = tid & 31, w = tid >> 5;
    int grp = lane >> 2, tig = lane & 3;
    int wm = w & 3, wn = w >> 2;

    float acc[2][4][4];
#pragma unroll
    for (int i = 0; i < 2; i++)
#pragma unroll
        for (int j = 0; j < 4; j++)
#pragma unroll
            for (int e = 0; e < 4; e++) acc[i][j][e] = 0.f;

    for (int k0 = 0; k0 < K; k0 += BK) {
        // A tile: 128 rows x 16 k-pairs
#pragma unroll
        for (int it = 0; it < 8; it++) {
            int pi = tid + it * 256;
            int mm = pi >> 4, kp = pi & 15;
            int gm = tile_m + mm, gk = k0 + kp * 2;
            float x0 = 0.f, x1 = 0.f;
            if (gm < M) {
                const float* ar = A + (long)gm * K;
                if (gk < K)     x0 = ar[gk];
                if (gk + 1 < K) x1 = ar[gk + 1];
            }
            unsigned lo, hi = splitpack(x0, x1, lo);
            Ah[kp][mm] = hi; Al[kp][mm] = lo;
        }
        // B tile: 16 k-pairs x 64 cols
#pragma unroll
        for (int it = 0; it < 4; it++) {
            int pi = tid + it * 256;
            int nn = pi & 63, kp = pi >> 6;
            int gn = tile_n + nn, gk = k0 + kp * 2;
            float x0 = 0.f, x1 = 0.f;
            if (gn < N) {
                if (gk < K)     x0 = W[(long)gk * N + gn];
                if (gk + 1 < K) x1 = W[(long)(gk + 1) * N + gn];
            }
            unsigned lo, hi = splitpack(x0, x1, lo);
            Bh[kp][nn] = hi; Bl[kp][nn] = lo;
        }
        __syncthreads();

#pragma unroll
        for (int s2 = 0; s2 < 2; s2++) {
            int kb = s2 * 8;
            unsigned ah[2][4], al[2][4], bh[4][2], bl[4][2];
#pragma unroll
            for (int i = 0; i < 2; i++) {
                int rb = wm * 32 + i * 16 + grp;
                ah[i][0] = Ah[kb + tig][rb];     ah[i][1] = Ah[kb + tig][rb + 8];
                ah[i][2] = Ah[kb + tig + 4][rb]; ah[i][3] = Ah[kb + tig + 4][rb + 8];
                al[i][0] = Al[kb + tig][rb];     al[i][1] = Al[kb + tig][rb + 8];
                al[i][2] = Al[kb + tig + 4][rb]; al[i][3] = Al[kb + tig + 4][rb + 8];
            }
#pragma unroll
            for (int j = 0; j < 4; j++) {
                int nb = wn * 32 + j * 8 + grp;
                bh[j][0] = Bh[kb + tig][nb]; bh[j][1] = Bh[kb + tig + 4][nb];
                bl[j][0] = Bl[kb + tig][nb]; bl[j][1] = Bl[kb + tig + 4][nb];
            }
#pragma unroll
            for (int i = 0; i < 2; i++)
#pragma unroll
                for (int j = 0; j < 4; j++) {
                    mma16(acc[i][j], ah[i], bh[j]);
                    mma16(acc[i][j], al[i], bh[j]);
                    mma16(acc[i][j], ah[i], bl[j]);
                }
        }
        __syncthreads();
    }

    // epilogue: bias + activation
#pragma unroll
    for (int i = 0; i < 2; i++) {
        int row0 = tile_m + wm * 32 + i * 16 + grp;
        int row1 = row0 + 8;
#pragma unroll
        for (int j = 0; j < 4; j++) {
            int col = tile_n + wn * 32 + j * 8 + tig * 2;
            if (col < N) {
                float b0v = bias[col], b1v = bias[col + 1];
                float v00 = acc[i][j][0] + b0v, v01 = acc[i][j][1] + b1v;
                float v10 = acc[i][j][2] + b0v, v11 = acc[i][j][3] + b1v;
                if (first) {
                    if (ACTOUT0 == 1) { v00 = fmaxf(v00, 0.f); v01 = fmaxf(v01, 0.f); v10 = fmaxf(v10, 0.f); v11 = fmaxf(v11, 0.f); }
                    else if (ACTOUT0 == 2) { v00 = tanhf(v00); v01 = tanhf(v01); v10 = tanhf(v10); v11 = tanhf(v11); }
                } else {
                    if (ACTOUT1 == 1) { v00 = fmaxf(v00, 0.f); v01 = fmaxf(v01, 0.f); v10 = fmaxf(v10, 0.f); v11 = fmaxf(v11, 0.f); }
                    else if (ACTOUT1 == 2) { v00 = tanhf(v00); v01 = tanhf(v01); v10 = tanhf(v10); v11 = tanhf(v11); }
                }
                if (row0 < M) { C[(long)row0 * N + col] = v00; C[(long)row0 * N + col + 1] = v01; }
                if (row1 < M) { C[(long)row1 * N + col] = v10; C[(long)row1 * N + col + 1] = v11; }
            }
        }
    }
}

// ---------------- flow output layer: warp per row, N=3, s+t fused ----------------
// hs/ht are POST-activation (stored by GEMM epilogue), so plain dot products.
__global__ void k_outrow(const float* __restrict__ hs, const float* __restrict__ ht,
                         const float* __restrict__ sw, const float* __restrict__ sb,
                         const float* __restrict__ tw, const float* __restrict__ tb) {
    __shared__ float Ws[2][HDIM * VV];
    __shared__ float Wb[2][VV];
    int tid = threadIdx.x;
    for (int i = tid; i < HDIM * VV; i += 256) { Ws[0][i] = sw[i]; Ws[1][i] = tw[i]; }
    if (tid < VV) { Wb[0][tid] = sb[tid]; Wb[1][tid] = tb[tid]; }
    __syncthreads();

    int wi = blockIdx.x * 8 + (tid >> 5);     // 0..15599
    int lane = tid & 31;
    int net = (wi >= MQ) ? 1 : 0;
    int r = net ? (wi - MQ) : wi;
    const float* Ar = (net ? ht : hs) + (long)r * HDIM;
    const float* Wn = Ws[net];
    float a0 = 0.f, a1 = 0.f, a2 = 0.f;
    for (int c = lane; c < HDIM; c += 32) {
        float a = Ar[c];
        a0 += a * Wn[c * 3 + 0];
        a1 += a * Wn[c * 3 + 1];
        a2 += a * Wn[c * 3 + 2];
    }
#pragma unroll
    for (int o = 16; o; o >>= 1) {
        a0 += __shfl_xor_sync(0xffffffffu, a0, o);
        a1 += __shfl_xor_sync(0xffffffffu, a1, o);
        a2 += __shfl_xor_sync(0xffffffffu, a2, o);
    }
    if (lane == 0) {
        float* C = net ? g_t : g_s;
        C[r * 3 + 0] = a0 + Wb[net][0];
        C[r * 3 + 1] = a1 + Wb[net][1];
        C[r * 3 + 2] = a2 + Wb[net][2];
    }
}

// ---------------- attention: block per (b,h), K/V in smem, all 12 queries ----------------
__global__ void k_attn2(const float* __restrict__ keys, const float* __restrict__ vals, int l) {
    int h = blockIdx.x & 7, b = blockIdx.x >> 3;
    int tid = threadIdx.x, lane = tid & 31, wq = tid >> 5;
    __shared__ float KsT[DD * TT];       // [d][w], pitch 48
    __shared__ float Vs[TT * DD];        // [w][d] row-major
    __shared__ float Qs[T2_ * DD];
    __shared__ float Ps[4][64];

    long base = ((long)(l * HH + h) * MKV + (long)b * TT) * DD;
    const float4* k4 = (const float4*)(keys + base);
    const float4* v4 = (const float4*)(vals + base);
    for (int i = tid; i < TT * DD / 4; i += 128) {
        float4 kv = k4[i];
        int w = i >> 4, d = (i & 15) << 2;
        KsT[(d + 0) * TT + w] = kv.x;
        KsT[(d + 1) * TT + w] = kv.y;
        KsT[(d + 2) * TT + w] = kv.z;
        KsT[(d + 3) * TT + w] = kv.w;
        ((float4*)Vs)[i] = v4[i];
    }
    for (int i = tid; i < T2_ * DD / 4; i += 128) {
        int q = i >> 4, d4 = (i & 15);
        ((float4*)Qs)[i] = *(const float4*)(g_attval + (long)(b * T2_ + q) * HDIM + h * DD + d4 * 4);
    }
    __syncthreads();

#pragma unroll
    for (int qi = 0; qi < 3; qi++) {
        int q = wq + qi * 4;
        int lim = (TT - T2_) + q;
        float d0 = 0.f, d1 = 0.f;
        const float* qrow = Qs + q * DD;
#pragma unroll
        for (int d = 0; d < DD; d++) {
            float qd = qrow[d];
            d0 += qd * KsT[d * TT + lane];
            d1 += qd * KsT[d * TT + ((lane + 32) & 63)];   // safe index; masked below
        }
        float s0 = (lane < lim) ? d0 * 0.125f : -1e30f;
        float s1 = (lane + 32 < lim) ? d1 * 0.125f : -1e30f;
        float mx = fmaxf(s0, s1);
#pragma unroll
        for (int o = 16; o; o >>= 1) mx = fmaxf(mx, __shfl_xor_sync(0xffffffffu, mx, o));
        float e0 = (lane < lim) ? expf(s0 - mx) : 0.f;
        float e1 = (lane + 32 < lim) ? expf(s1 - mx) : 0.f;
        float sm = e0 + e1;
#pragma unroll
        for (int o = 16; o; o >>= 1) sm += __shfl_xor_sync(0xffffffffu, sm, o);
        Ps[wq][lane] = e0;
        Ps[wq][lane + 32] = e1;
        __syncwarp();
        float inv = 1.f / sm;
        float o0 = 0.f, o1 = 0.f;
        for (int w2 = 0; w2 < lim; w2++) {
            float p = Ps[wq][w2];
            o0 += p * Vs[w2 * DD + lane];
            o1 += p * Vs[w2 * DD + lane + 32];
        }
        long orow = (long)(b * T2_ + q) * HDIM + h * DD;
        g_att[orow + lane] = o0 * inv;
        g_att[orow + lane + 32] = o1 * inv;
        __syncwarp();
    }
}

// ---------------- add + layernorm ----------------
__global__ void k_add_ln(float* __restrict__ x, const float* __restrict__ y,
                         const float* __restrict__ gamma, const float* __restrict__ beta) {
    int m = blockIdx.x;
    int tid = threadIdx.x;
    long base = (long)m * HDIM;
    float v0 = x[base + tid] + y[base + tid];
    float v1 = x[base + 256 + tid] + y[base + 256 + tid];
    __shared__ float red[256];
    __shared__ float s_mean, s_rstd;
    red[tid] = v0 + v1;
    __syncthreads();
    for (int st = 128; st > 0; st >>= 1) {
        if (tid < st) red[tid] += red[tid + st];
        __syncthreads();
    }
    if (tid == 0) s_mean = red[0] / (float)HDIM;
    __syncthreads();
    float mn = s_mean;
    float d0 = v0 - mn, d1 = v1 - mn;
    red[tid] = d0 * d0 + d1 * d1;
    __syncthreads();
    for (int st = 128; st > 0; st >>= 1) {
        if (tid < st) red[tid] += red[tid + st];
        __syncthreads();
    }
    if (tid == 0) s_rstd = rsqrtf(red[0] / (float)HDIM + 1e-5f);
    __syncthreads();
    float r = s_rstd;
    x[base + tid]       = d0 * r * gamma[tid]       + beta[tid];
    x[base + 256 + tid] = d1 * r * gamma[256 + tid] + beta[256 + tid];
}

// ---------------- host orchestration ----------------
static inline int ceildiv(int a, int b) { return (a + b - 1) / b; }

extern "C" void kernel_launch(void* const* d_in, const int* in_sizes, int n_in,
                              void* d_out, int out_size) {
    const float* encoded   = (const float*)d_in[0];
    const float* true_val  = (const float*)d_in[1];
    const float* W_shift   = (const float*)d_in[2];
    const float* b_shift   = (const float*)d_in[3];
    const float* W_key     = (const float*)d_in[4];
    const float* b_key     = (const float*)d_in[5];
    const float* W_val     = (const float*)d_in[6];
    const float* b_val     = (const float*)d_in[7];
    const float* ln1_s     = (const float*)d_in[8];
    const float* ln1_b     = (const float*)d_in[9];
    const float* ff_w1     = (const float*)d_in[10];
    const float* ff_b1     = (const float*)d_in[11];
    const float* ff_w2     = (const float*)d_in[12];
    const float* ff_b2     = (const float*)d_in[13];
    const float* ln2_s     = (const float*)d_in[14];
    const float* ln2_b     = (const float*)d_in[15];
    const float* s_w_in    = (const float*)d_in[16];
    const float* s_b_in    = (const float*)d_in[17];
    const float* s_w_hid   = (const float*)d_in[18];
    const float* s_b_hid   = (const float*)d_in[19];
    const float* s_w_out   = (const float*)d_in[20];
    const float* s_b_out   = (const float*)d_in[21];
    const float* t_w_in    = (const float*)d_in[22];
    const float* t_b_in    = (const float*)d_in[23];
    const float* t_w_hid   = (const float*)d_in[24];
    const float* t_b_hid   = (const float*)d_in[25];
    const float* t_w_out   = (const float*)d_in[26];
    const float* t_b_out   = (const float*)d_in[27];
    const float* bn_lg     = (const float*)d_in[28];
    const float* bn_bt     = (const float*)d_in[29];

    float *ev, *keys, *vals, *attin, *attval, *att, *h1, *h2, *h3, *h4, *inp;
    cudaGetSymbolAddress((void**)&ev,     g_ev);
    cudaGetSymbolAddress((void**)&keys,   g_keys);
    cudaGetSymbolAddress((void**)&vals,   g_vals);
    cudaGetSymbolAddress((void**)&attin,  g_attin);
    cudaGetSymbolAddress((void**)&attval, g_attval);
    cudaGetSymbolAddress((void**)&att,    g_att);
    cudaGetSymbolAddress((void**)&h1,     g_h1);
    cudaGetSymbolAddress((void**)&h2,     g_h2);
    cudaGetSymbolAddress((void**)&h3,     g_h3);
    cudaGetSymbolAddress((void**)&h4,     g_h4);
    cudaGetSymbolAddress((void**)&inp,    g_inp);

    // 1) build ev and att_in
    k_build_ev<<<ceildiv(MKV * DIN_, 256), 256>>>(encoded, true_val);
    k_build_attin<<<ceildiv(MQ * VV * CC, 256), 256>>>(encoded);

    // 2) K and V projections fused: 64 z-slices of [31200,387]@[387,64]
    {
        dim3 g(1, ceildiv(MKV, BM), 2 * LLAY * HH);
        k_mma2<0,0><<<g, 256>>>(ev, W_key, b_key, keys,
                                ev, W_val, b_val, vals,
                                MKV, DD, DIN_, LLAY * HH,
                                0L, (long)DIN_ * DD, (long)DD, (long)MKV * DD);
    }

    // 3) att_value = att_in @ W_shift + b_shift
    {
        dim3 g(HDIM / BN, ceildiv(MQ, BM), 1);
        k_mma2<0,0><<<g, 256>>>(attin, W_shift, b_shift, attval,
                                attin, W_shift, b_shift, attval,
                                MQ, HDIM, VV * CC, 1, 0L, 0L, 0L, 0L);
    }

    // 4) transformer layers
    for (int l = 0; l < LLAY; l++) {
        k_attn2<<<BNN * HH, 128>>>(keys, vals, l);
        k_add_ln<<<MQ, 256>>>(attval, att, ln1_s + (long)l * HDIM, ln1_b + (long)l * HDIM);
        dim3 g(HDIM / BN, ceildiv(MQ, BM), 1);
        // ff1 with relu stored in epilogue
        k_mma2<1,1><<<g, 256>>>(attval, ff_w1 + (long)l * HDIM * HDIM, ff_b1 + (long)l * HDIM, h1,
                                attval, ff_w1 + (long)l * HDIM * HDIM, ff_b1 + (long)l * HDIM, h1,
                                MQ, HDIM, HDIM, 1, 0L, 0L, 0L, 0L);
        k_mma2<0,0><<<g, 256>>>(h1, ff_w2 + (long)l * HDIM * HDIM, ff_b2 + (long)l * HDIM, att,
                                h1, ff_w2 + (long)l * HDIM * HDIM, ff_b2 + (long)l * HDIM, att,
                                MQ, HDIM, HDIM, 1, 0L, 0L, 0L, 0L);
        k_add_ln<<<MQ, 256>>>(attval, att, ln2_s + (long)l * HDIM, ln2_b + (long)l * HDIM);
    }

    // 5) RealNVP flow
    k_build_inp_y<<<ceildiv(MQ * HDIM, 256), 256>>>();
    k_init_u_mu<<<ceildiv(MQ * VV, 256), 256>>>(true_val);

    dim3 gd(HDIM / BN, ceildiv(MQ, BM), 2);   // dual s/t net GEMMs

    for (int blk = 0; blk < NB_; blk++) {
        // layer 0 (input 515): s stores tanh, t stores relu
        k_mma2<2,1><<<gd, 256>>>(inp, s_w_in + (long)blk * CY_ * HDIM, s_b_in + (long)blk * HDIM, h1,
                                 inp, t_w_in + (long)blk * CY_ * HDIM, t_b_in + (long)blk * HDIM, h3,
                                 MQ, HDIM, CY_, 1, 0L, 0L, 0L, 0L);
        float* cs = h1; float* ns = h2;
        float* ct = h3; float* nt = h4;
        for (int i = 0; i < NHID_; i++) {
            k_mma2<2,1><<<gd, 256>>>(cs, s_w_hid + ((long)blk * NHID_ + i) * HDIM * HDIM,
                                         s_b_hid + ((long)blk * NHID_ + i) * HDIM, ns,
                                     ct, t_w_hid + ((long)blk * NHID_ + i) * HDIM * HDIM,
                                         t_b_hid + ((long)blk * NHID_ + i) * HDIM, nt,
                                     MQ, HDIM, HDIM, 1, 0L, 0L, 0L, 0L);
            float* tmp = cs; cs = ns; ns = tmp;
            tmp = ct; ct = nt; nt = tmp;
        }
        // output layer: N=3, warp-per-row, both nets
        k_outrow<<<(2 * MQ) / 8, 256>>>(cs, ct,
                                        s_w_out + (long)blk * HDIM * VV, s_b_out + (long)blk * VV,
                                        t_w_out + (long)blk * HDIM * VV, t_b_out + (long)blk * VV);
        k_coupling_stats<<<T2_ * VV, 256>>>(blk);
        k_bn_apply_mu<<<ceildiv(MQ * VV, 256), 256>>>(bn_lg + (long)blk * VV, bn_bt + (long)blk * VV, blk);
    }

    // 6) final NLL
    k_final<<<ceildiv(BNN, 256), 256>>>((float*)d_out);
}

// round 4
// speedup vs baseline: 3.3399x; 2.5271x over previous
#include <cuda_runtime.h>
#include <cuda_bf16.h>
#include <math.h>

// ---------------- problem dims ----------------
#define NV_   975
#define TT    48
#define T2_   12
#define CC    128
#define VV    3
#define HH    8
#define DD    64
#define HDIM  512
#define LLAY  4
#define NB_   6
#define NHID_ 4
#define DIN_  387
#define NVG   325
#define BNN   650
#define MKV   (BNN*TT)   // 31200
#define MQ    (BNN*T2_)  // 7800
#define LOG2PI_F 1.8378770664093453f

// padded k-pair counts (multiples of 16)
#define EVKP 208   // ceil(387/2)=194 -> 208
#define AIKP 192   // 384/2
#define HKP  256   // 512/2
#define INKP 272   // ceil(515/2)=258 -> 272

// ---------------- fp32 scratch ----------------
__device__ float g_keys[LLAY*HH*MKV*DD];
__device__ float g_vals[LLAY*HH*MKV*DD];
__device__ float g_attval[MQ*HDIM];
__device__ float g_att[MQ*HDIM];
__device__ float g_s[MQ*VV];
__device__ float g_t[MQ*VV];
__device__ float g_u[MQ*VV];
__device__ float g_ld[MQ*VV];
__device__ float g_bnstats[T2_*VV*2];

// ---------------- packed bf16 hi/lo activation planes ----------------
__device__ unsigned a_ev_h[MKV*EVKP], a_ev_l[MKV*EVKP];
__device__ unsigned a_ai_h[MQ*AIKP],  a_ai_l[MQ*AIKP];
__device__ unsigned a_av_h[MQ*HKP],   a_av_l[MQ*HKP];
__device__ unsigned a_h1h[MQ*HKP], a_h1l[MQ*HKP];
__device__ unsigned a_h2h[MQ*HKP], a_h2l[MQ*HKP];
__device__ unsigned a_h3h[MQ*HKP], a_h3l[MQ*HKP];
__device__ unsigned a_h4h[MQ*HKP], a_h4l[MQ*HKP];
__device__ unsigned a_inh[MQ*INKP], a_inl[MQ*INKP];

// ---------------- packed weight planes ----------------
__device__ unsigned w_sh_h[AIKP*HDIM], w_sh_l[AIKP*HDIM];
__device__ unsigned w_f1_h[LLAY*HKP*HDIM], w_f1_l[LLAY*HKP*HDIM];
__device__ unsigned w_f2_h[LLAY*HKP*HDIM], w_f2_l[LLAY*HKP*HDIM];
__device__ unsigned w_in_h[2*NB_*INKP*HDIM], w_in_l[2*NB_*INKP*HDIM];
__device__ unsigned w_hd_h[2*NB_*NHID_*HKP*HDIM], w_hd_l[2*NB_*NHID_*HKP*HDIM];
__device__ unsigned w_kv_h[2*LLAY*HH*EVKP*DD], w_kv_l[2*LLAY*HH*EVKP*DD];

// ---------------- helpers ----------------
__device__ __forceinline__ unsigned splitpack(float x0, float x1, unsigned& lo) {
    __nv_bfloat16 h0 = __float2bfloat16_rn(x0);
    __nv_bfloat16 h1 = __float2bfloat16_rn(x1);
    float r0 = x0 - __bfloat162float(h0);
    float r1 = x1 - __bfloat162float(h1);
    __nv_bfloat162 hp = __halves2bfloat162(h0, h1);
    __nv_bfloat162 lp = __halves2bfloat162(__float2bfloat16_rn(r0), __float2bfloat16_rn(r1));
    lo = *reinterpret_cast<unsigned*>(&lp);
    return *reinterpret_cast<unsigned*>(&hp);
}

__device__ __forceinline__ float2 unpack2(unsigned h, unsigned l) {
    __nv_bfloat162 hb = *reinterpret_cast<__nv_bfloat162*>(&h);
    __nv_bfloat162 lb = *reinterpret_cast<__nv_bfloat162*>(&l);
    float2 r;
    r.x = __bfloat162float(hb.x) + __bfloat162float(lb.x);
    r.y = __bfloat162float(hb.y) + __bfloat162float(lb.y);
    return r;
}

__device__ __forceinline__ void cpa16(void* dst, const void* src) {
    unsigned d = (unsigned)__cvta_generic_to_shared(dst);
    asm volatile("cp.async.cg.shared.global [%0], [%1], 16;" :: "r"(d), "l"(src));
}

__device__ __forceinline__ void mma16(float* c, const unsigned* a, const unsigned* b) {
    asm volatile(
        "mma.sync.aligned.m16n8k16.row.col.f32.bf16.bf16.f32 "
        "{%0,%1,%2,%3}, {%4,%5,%6,%7}, {%8,%9}, {%0,%1,%2,%3};"
        : "+f"(c[0]), "+f"(c[1]), "+f"(c[2]), "+f"(c[3])
        : "r"(a[0]), "r"(a[1]), "r"(a[2]), "r"(a[3]), "r"(b[0]), "r"(b[1]));
}

template <int A> __device__ __forceinline__ float actf(float v) {
    if (A == 1) return fmaxf(v, 0.f);
    if (A == 2) return tanhf(v);
    return v;
}

// ---------------- weight pre-conversion ----------------
// src fp32 [Z][K][N] -> hi/lo planes [Z][KP2][N] (k-pairs packed, zero-padded)
__global__ void k_convw(const float* __restrict__ src, unsigned* __restrict__ dhi,
                        unsigned* __restrict__ dlo, int K, int N, int KP2) {
    long z = blockIdx.z;
    src += z * (long)K * N;
    dhi += z * (long)KP2 * N;
    dlo += z * (long)KP2 * N;
    int idx = blockIdx.x * 256 + threadIdx.x;
    if (idx >= KP2 * N) return;
    int kp = idx / N, n = idx - kp * N;
    float x0 = (2 * kp     < K) ? src[(long)(2 * kp) * N + n]     : 0.f;
    float x1 = (2 * kp + 1 < K) ? src[(long)(2 * kp + 1) * N + n] : 0.f;
    unsigned lo, hi = splitpack(x0, x1, lo);
    dhi[idx] = hi; dlo[idx] = lo;
}

// ---------------- builders (emit packed planes) ----------------
__global__ void k_build_ev(const float* __restrict__ enc, const float* __restrict__ tv) {
    long idx = (long)blockIdx.x * 256 + threadIdx.x;
    if (idx >= (long)MKV * EVKP) return;
    int kp = (int)(idx % EVKP);
    int m  = (int)(idx / EVKP);
    int b = m / TT, tt = m % TT;
    int ob = b / NVG, nvb = (b % NVG) * VV;
    float x[2];
#pragma unroll
    for (int t = 0; t < 2; t++) {
        int e = 2 * kp + t;
        float v = 0.f;
        if (e < DIN_) {
            int vv = e / (CC + 1), cc = e % (CC + 1);
            int nv = nvb + vv;
            if (cc < CC) v = enc[(((long)ob * NV_ + nv) * TT + tt) * CC + cc];
            else         v = tv[((long)ob * NV_ + nv) * TT + tt];
        }
        x[t] = v;
    }
    unsigned lo, hi = splitpack(x[0], x[1], lo);
    a_ev_h[idx] = hi; a_ev_l[idx] = lo;
}

__global__ void k_build_attin(const float* __restrict__ enc) {
    long idx = (long)blockIdx.x * 256 + threadIdx.x;
    if (idx >= (long)MQ * AIKP) return;
    int kp = (int)(idx % AIKP);
    int m  = (int)(idx / AIKP);
    int b = m / T2_, q = m % T2_;
    int ob = b / NVG, nvb = (b % NVG) * VV;
    float x[2];
#pragma unroll
    for (int t = 0; t < 2; t++) {
        int e = 2 * kp + t;        // < 384
        int vv = e / CC, cc = e % CC;
        x[t] = enc[(((long)ob * NV_ + nvb + vv) * TT + (TT - T2_) + q) * CC + cc];
    }
    unsigned lo, hi = splitpack(x[0], x[1], lo);
    a_ai_h[idx] = hi; a_ai_l[idx] = lo;
}

// copy attval planes into inp y-region, zero tail padding
__global__ void k_build_inp_y() {
    long idx = (long)blockIdx.x * 256 + threadIdx.x;
    if (idx >= (long)MQ * INKP) return;
    int kp = (int)(idx % INKP);
    int m  = (int)(idx / INKP);
    if (kp < HKP) {
        a_inh[idx] = a_av_h[(long)m * HKP + kp];
        a_inl[idx] = a_av_l[(long)m * HKP + kp];
    } else if (kp >= 258) {
        a_inh[idx] = 0u; a_inl[idx] = 0u;
    }
    // kp 256,257 (mu) written by mu kernels
}

__global__ void k_init_u_mu(const float* __restrict__ tv) {
    int m = blockIdx.x * 256 + threadIdx.x;
    if (m >= MQ) return;
    int b = m / T2_, q = m % T2_;
    int ob = b / NVG, nvb = (b % NVG) * VV;
    float u[3];
#pragma unroll
    for (int v = 0; v < 3; v++) {
        u[v] = tv[((long)ob * NV_ + nvb + v) * TT + (TT - T2_) + q];
        g_u[m * 3 + v] = u[v];
        g_ld[m * 3 + v] = 0.f;
    }
    // blk 0 mask: keep odd v
    unsigned lo, hi;
    hi = splitpack(0.f, u[1], lo);
    a_inh[(long)m * INKP + 256] = hi; a_inl[(long)m * INKP + 256] = lo;
    hi = splitpack(0.f, 0.f, lo);
    a_inh[(long)m * INKP + 257] = hi; a_inl[(long)m * INKP + 257] = lo;
}

// coupling transform fused with batch-norm statistics
__global__ void k_coupling_stats(int blk) {
    int col = blockIdx.x;          // 0..35
    int v   = col % VV;
    int mask = (v + blk) & 1;
    int tid = threadIdx.x;
    __shared__ float rs[256], rq[256];
    float s = 0.f, q = 0.f;
    for (int b = tid; b < BNN; b += 256) {
        int e = b * (T2_ * VV) + col;
        float u = g_u[e];
        if (!mask) {
            float sv = g_s[e];
            u = (u - g_t[e]) * expf(-sv);
            g_u[e] = u;
            g_ld[e] -= sv;
        }
        s += u; q += u * u;
    }
    rs[tid] = s; rq[tid] = q;
    __syncthreads();
    for (int st = 128; st > 0; st >>= 1) {
        if (tid < st) { rs[tid] += rs[tid + st]; rq[tid] += rq[tid + st]; }
        __syncthreads();
    }
    if (tid == 0) {
        float mean = rs[0] / (float)BNN;
        float var  = rq[0] / (float)BNN - mean * mean;
        g_bnstats[col * 2 + 0] = mean;
        g_bnstats[col * 2 + 1] = var;
    }
}

// BN apply fused with next block's masked-mu plane write (one thread per row)
__global__ void k_bn_apply_mu(const float* __restrict__ lgam, const float* __restrict__ beta, int blk) {
    int m = blockIdx.x * 256 + threadIdx.x;
    if (m >= MQ) return;
    int t2 = m % T2_;
    float mu[3];
#pragma unroll
    for (int v = 0; v < 3; v++) {
        int col = t2 * 3 + v;
        float mean = g_bnstats[col * 2 + 0];
        float var  = g_bnstats[col * 2 + 1];
        float lg = lgam[v], bt = beta[v];
        float u = expf(lg) * (g_u[m * 3 + v] - mean) * rsqrtf(var + 1e-5f) + bt;
        g_u[m * 3 + v] = u;
        g_ld[m * 3 + v] += lg - 0.5f * logf(var + 1e-5f);
        int nmask = (v + blk + 1) & 1;
        mu[v] = nmask ? u : 0.f;
    }
    if (blk < NB_ - 1) {
        unsigned lo, hi;
        hi = splitpack(mu[0], mu[1], lo);
        a_inh[(long)m * INKP + 256] = hi; a_inl[(long)m * INKP + 256] = lo;
        hi = splitpack(mu[2], 0.f, lo);
        a_inh[(long)m * INKP + 257] = hi; a_inl[(long)m * INKP + 257] = lo;
    }
}

__global__ void k_final(float* __restrict__ out) {
    int b = blockIdx.x * 256 + threadIdx.x;
    if (b >= BNN) return;
    float acc = 0.f;
    for (int i = 0; i < T2_ * VV; i++) {
        float u = g_u[b * (T2_ * VV) + i];
        acc += 0.5f * u * u + 0.5f * LOG2PI_F - g_ld[b * (T2_ * VV) + i];
    }
    out[b] = acc;
}

// ---------------- pipelined bf16x3 tensor-core GEMM ----------------
// Operands preconverted to packed hi/lo planes. cp.async double buffered.
// Block tile 128x64, 16 k-pairs (K=32) per stage, 256 threads (8 warps, 32x32 each).
#define BM 128
#define BN 64
#define KPITER 16
#define APITCH 20
#define BPITCH 72
#define ABASE (2*2*BM*APITCH)             // uints
#define SMEMSZ ((ABASE + 2*2*KPITER*BPITCH)*4)

template <int ACT0, int ACT1>
__global__ void __launch_bounds__(256, 2)
k_mma(const unsigned* __restrict__ Ah0, const unsigned* __restrict__ Al0,
      const unsigned* __restrict__ Wh0, const unsigned* __restrict__ Wl0,
      const float* __restrict__ b0, float* __restrict__ C0,
      unsigned* __restrict__ Ph0, unsigned* __restrict__ Pl0,
      const unsigned* __restrict__ Ah1, const unsigned* __restrict__ Al1,
      const unsigned* __restrict__ Wh1, const unsigned* __restrict__ Wl1,
      const float* __restrict__ b1, float* __restrict__ C1,
      unsigned* __restrict__ Ph1, unsigned* __restrict__ Pl1,
      int M, int N, int KP2, int z0,
      long sW, long sb, long sC) {
    extern __shared__ __align__(16) unsigned dsm[];
    // As[st][p][m][APITCH] ; Bs[st][p][kp][BPITCH]

    bool first = ((int)blockIdx.z < z0);
    int zl = first ? blockIdx.z : blockIdx.z - z0;
    const unsigned* Ahp = first ? Ah0 : Ah1;
    const unsigned* Alp = first ? Al0 : Al1;
    const unsigned* Whp = (first ? Wh0 : Wh1) + (long)zl * sW;
    const unsigned* Wlp = (first ? Wl0 : Wl1) + (long)zl * sW;
    const float* bias   = (first ? b0 : b1) + (long)zl * sb;
    float* C            = (first ? C0 : C1);
    if (C) C += (long)zl * sC;
    unsigned* Ph = first ? Ph0 : Ph1;
    unsigned* Pl = first ? Pl0 : Pl1;

    int tile_m = blockIdx.y * BM;
    int tile_n = blockIdx.x * BN;
    int tid = threadIdx.x, lane = tid & 31, w = tid >> 5;
    int grp = lane >> 2, tig = lane & 3;
    int wm = w & 3, wn = w >> 2;

    float acc[2][4][4];
#pragma unroll
    for (int i = 0; i < 2; i++)
#pragma unroll
        for (int j = 0; j < 4; j++)
#pragma unroll
            for (int e = 0; e < 4; e++) acc[i][j][e] = 0.f;

    auto load_stage = [&](int st, int k0p) {
        // A tiles: 2 planes x 128 rows x 16 kpairs, 16B chunks (4 kpairs)
#pragma unroll
        for (int c4 = 0; c4 < 4; c4++) {
            int c = tid + c4 * 256;
            int p = c >> 9; int rem = c & 511;
            int rr = rem >> 2; int ck = (rem & 3) << 2;
            int gm = tile_m + rr; if (gm >= M) gm = M - 1;
            const unsigned* src = (p ? Alp : Ahp) + (long)gm * KP2 + k0p + ck;
            cpa16(&dsm[((p * BM + rr) + st * 2 * BM) * APITCH + ck], src);
        }
        // B tiles: 2 planes x 16 kp x 64 n
#pragma unroll
        for (int c2 = 0; c2 < 2; c2++) {
            int c = tid + c2 * 256;
            int p = c >> 8; int rem = c & 255;
            int kp = rem >> 4; int nb = (rem & 15) << 2;
            const unsigned* src = (p ? Wlp : Whp) + (long)(k0p + kp) * N + tile_n + nb;
            cpa16(&dsm[ABASE + ((st * 2 + p) * KPITER + kp) * BPITCH + nb], src);
        }
        asm volatile("cp.async.commit_group;");
    };

    int iters = KP2 / KPITER;
    load_stage(0, 0);

    for (int it = 0; it < iters; it++) {
        if (it + 1 < iters) {
            load_stage((it + 1) & 1, (it + 1) * KPITER);
            asm volatile("cp.async.wait_group 1;");
        } else {
            asm volatile("cp.async.wait_group 0;");
        }
        __syncthreads();

        int st = it & 1;
        const unsigned* As0 = &dsm[(st * 2 + 0) * BM * APITCH];
        const unsigned* As1 = &dsm[(st * 2 + 1) * BM * APITCH];
        const unsigned* Bs0 = &dsm[ABASE + (st * 2 + 0) * KPITER * BPITCH];
        const unsigned* Bs1 = &dsm[ABASE + (st * 2 + 1) * KPITER * BPITCH];

#pragma unroll
        for (int s2 = 0; s2 < 2; s2++) {
            int kb = s2 * 8;
            unsigned ah[2][4], al[2][4], bh[4][2], bl[4][2];
#pragma unroll
            for (int i = 0; i < 2; i++) {
                int rb = wm * 32 + i * 16 + grp;
                ah[i][0] = As0[rb * APITCH + kb + tig];
                ah[i][1] = As0[(rb + 8) * APITCH + kb + tig];
                ah[i][2] = As0[rb * APITCH + kb + tig + 4];
                ah[i][3] = As0[(rb + 8) * APITCH + kb + tig + 4];
                al[i][0] = As1[rb * APITCH + kb + tig];
                al[i][1] = As1[(rb + 8) * APITCH + kb + tig];
                al[i][2] = As1[rb * APITCH + kb + tig + 4];
                al[i][3] = As1[(rb + 8) * APITCH + kb + tig + 4];
            }
#pragma unroll
            for (int j = 0; j < 4; j++) {
                int nb = wn * 32 + j * 8 + grp;
                bh[j][0] = Bs0[(kb + tig) * BPITCH + nb];
                bh[j][1] = Bs0[(kb + tig + 4) * BPITCH + nb];
                bl[j][0] = Bs1[(kb + tig) * BPITCH + nb];
                bl[j][1] = Bs1[(kb + tig + 4) * BPITCH + nb];
            }
#pragma unroll
            for (int i = 0; i < 2; i++)
#pragma unroll
                for (int j = 0; j < 4; j++) {
                    mma16(acc[i][j], ah[i], bh[j]);
                    mma16(acc[i][j], al[i], bh[j]);
                    mma16(acc[i][j], ah[i], bl[j]);
                }
        }
        __syncthreads();
    }

    // epilogue: bias + activation; optional fp32 C and packed-plane outputs
    int NP2 = N >> 1;
#pragma unroll
    for (int i = 0; i < 2; i++) {
        int row0 = tile_m + wm * 32 + i * 16 + grp;
        int row1 = row0 + 8;
#pragma unroll
        for (int j = 0; j < 4; j++) {
            int col = tile_n + wn * 32 + j * 8 + tig * 2;
            float b0v = bias[col], b1v = bias[col + 1];
            float v00 = acc[i][j][0] + b0v, v01 = acc[i][j][1] + b1v;
            float v10 = acc[i][j][2] + b0v, v11 = acc[i][j][3] + b1v;
            if (first) {
                v00 = actf<ACT0>(v00); v01 = actf<ACT0>(v01);
                v10 = actf<ACT0>(v10); v11 = actf<ACT0>(v11);
            } else {
                v00 = actf<ACT1>(v00); v01 = actf<ACT1>(v01);
                v10 = actf<ACT1>(v10); v11 = actf<ACT1>(v11);
            }
            if (C) {
                if (row0 < M) { C[(long)row0 * N + col] = v00; C[(long)row0 * N + col + 1] = v01; }
                if (row1 < M) { C[(long)row1 * N + col] = v10; C[(long)row1 * N + col + 1] = v11; }
            }
            if (Ph) {
                unsigned lo, hi;
                if (row0 < M) {
                    hi = splitpack(v00, v01, lo);
                    Ph[(long)row0 * NP2 + (col >> 1)] = hi;
                    Pl[(long)row0 * NP2 + (col >> 1)] = lo;
                }
                if (row1 < M) {
                    hi = splitpack(v10, v11, lo);
                    Ph[(long)row1 * NP2 + (col >> 1)] = hi;
                    Pl[(long)row1 * NP2 + (col >> 1)] = lo;
                }
            }
        }
    }
}

// ---------------- flow output layer: warp per row, N=3, s+t fused, reads planes ----------------
__global__ void k_outrow(const unsigned* __restrict__ hsh, const unsigned* __restrict__ hsl,
                         const unsigned* __restrict__ hth, const unsigned* __restrict__ htl,
                         const float* __restrict__ sw, const float* __restrict__ sb,
                         const float* __restrict__ tw, const float* __restrict__ tb) {
    __shared__ float Ws[2][HDIM * VV];
    __shared__ float Wb[2][VV];
    int tid = threadIdx.x;
    for (int i = tid; i < HDIM * VV; i += 256) { Ws[0][i] = sw[i]; Ws[1][i] = tw[i]; }
    if (tid < VV) { Wb[0][tid] = sb[tid]; Wb[1][tid] = tb[tid]; }
    __syncthreads();

    int wi = blockIdx.x * 8 + (tid >> 5);
    int lane = tid & 31;
    int net = (wi >= MQ) ? 1 : 0;
    int r = net ? (wi - MQ) : wi;
    const unsigned* Hh = net ? hth : hsh;
    const unsigned* Hl = net ? htl : hsl;
    const float* Wn = Ws[net];
    float a0 = 0.f, a1 = 0.f, a2 = 0.f;
    for (int cp = lane; cp < HKP; cp += 32) {
        float2 v = unpack2(Hh[(long)r * HKP + cp], Hl[(long)r * HKP + cp]);
        int c0 = 2 * cp;
        a0 += v.x * Wn[c0 * 3 + 0] + v.y * Wn[(c0 + 1) * 3 + 0];
        a1 += v.x * Wn[c0 * 3 + 1] + v.y * Wn[(c0 + 1) * 3 + 1];
        a2 += v.x * Wn[c0 * 3 + 2] + v.y * Wn[(c0 + 1) * 3 + 2];
    }
#pragma unroll
    for (int o = 16; o; o >>= 1) {
        a0 += __shfl_xor_sync(0xffffffffu, a0, o);
        a1 += __shfl_xor_sync(0xffffffffu, a1, o);
        a2 += __shfl_xor_sync(0xffffffffu, a2, o);
    }
    if (lane == 0) {
        float* Cp = net ? g_t : g_s;
        Cp[r * 3 + 0] = a0 + Wb[net][0];
        Cp[r * 3 + 1] = a1 + Wb[net][1];
        Cp[r * 3 + 2] = a2 + Wb[net][2];
    }
}

// ---------------- attention: block per (b,h), K/V in smem, 12 queries ----------------
__global__ void k_attn2(const float* __restrict__ keys, const float* __restrict__ vals, int l) {
    int h = blockIdx.x & 7, b = blockIdx.x >> 3;
    int tid = threadIdx.x, lane = tid & 31, wq = tid >> 5;
    __shared__ float KsT[DD * TT];
    __shared__ float Vs[TT * DD];
    __shared__ float Qs[T2_ * DD];
    __shared__ float Ps[4][64];

    long base = ((long)(l * HH + h) * MKV + (long)b * TT) * DD;
    const float4* k4 = (const float4*)(keys + base);
    const float4* v4 = (const float4*)(vals + base);
    for (int i = tid; i < TT * DD / 4; i += 128) {
        float4 kv = k4[i];
        int w = i >> 4, d = (i & 15) << 2;
        KsT[(d + 0) * TT + w] = kv.x;
        KsT[(d + 1) * TT + w] = kv.y;
        KsT[(d + 2) * TT + w] = kv.z;
        KsT[(d + 3) * TT + w] = kv.w;
        ((float4*)Vs)[i] = v4[i];
    }
    for (int i = tid; i < T2_ * DD / 4; i += 128) {
        int q = i >> 4, d4 = (i & 15);
        ((float4*)Qs)[i] = *(const float4*)(g_attval + (long)(b * T2_ + q) * HDIM + h * DD + d4 * 4);
    }
    __syncthreads();

#pragma unroll
    for (int qi = 0; qi < 3; qi++) {
        int q = wq + qi * 4;
        int lim = (TT - T2_) + q;
        float d0 = 0.f, d1 = 0.f;
        const float* qrow = Qs + q * DD;
#pragma unroll
        for (int d = 0; d < DD; d++) {
            float qd = qrow[d];
            d0 += qd * KsT[d * TT + lane];
            d1 += qd * KsT[d * TT + ((lane + 32) & 63)];
        }
        float s0 = (lane < lim) ? d0 * 0.125f : -1e30f;
        float s1 = (lane + 32 < lim) ? d1 * 0.125f : -1e30f;
        float mx = fmaxf(s0, s1);
#pragma unroll
        for (int o = 16; o; o >>= 1) mx = fmaxf(mx, __shfl_xor_sync(0xffffffffu, mx, o));
        float e0 = (lane < lim) ? expf(s0 - mx) : 0.f;
        float e1 = (lane + 32 < lim) ? expf(s1 - mx) : 0.f;
        float sm = e0 + e1;
#pragma unroll
        for (int o = 16; o; o >>= 1) sm += __shfl_xor_sync(0xffffffffu, sm, o);
        Ps[wq][lane] = e0;
        Ps[wq][lane + 32] = e1;
        __syncwarp();
        float inv = 1.f / sm;
        float o0 = 0.f, o1 = 0.f;
        for (int w2 = 0; w2 < lim; w2++) {
            float p = Ps[wq][w2];
            o0 += p * Vs[w2 * DD + lane];
            o1 += p * Vs[w2 * DD + lane + 32];
        }
        long orow = (long)(b * T2_ + q) * HDIM + h * DD;
        g_att[orow + lane] = o0 * inv;
        g_att[orow + lane + 32] = o1 * inv;
        __syncwarp();
    }
}

// ---------------- add + layernorm; emits fp32 and packed planes ----------------
__global__ void k_add_ln(float* __restrict__ x, const float* __restrict__ y,
                         const float* __restrict__ gamma, const float* __restrict__ beta) {
    int m = blockIdx.x;
    int tid = threadIdx.x;
    long base = (long)m * HDIM;
    float2 xx = *(const float2*)&x[base + 2 * tid];
    float2 yy = *(const float2*)&y[base + 2 * tid];
    float v0 = xx.x + yy.x, v1 = xx.y + yy.y;
    __shared__ float red[256];
    __shared__ float s_mean, s_rstd;
    red[tid] = v0 + v1;
    __syncthreads();
    for (int st = 128; st > 0; st >>= 1) {
        if (tid < st) red[tid] += red[tid + st];
        __syncthreads();
    }
    if (tid == 0) s_mean = red[0] / (float)HDIM;
    __syncthreads();
    float mn = s_mean;
    float d0 = v0 - mn, d1 = v1 - mn;
    red[tid] = d0 * d0 + d1 * d1;
    __syncthreads();
    for (int st = 128; st > 0; st >>= 1) {
        if (tid < st) red[tid] += red[tid + st];
        __syncthreads();
    }
    if (tid == 0) s_rstd = rsqrtf(red[0] / (float)HDIM + 1e-5f);
    __syncthreads();
    float r = s_rstd;
    float o0 = d0 * r * gamma[2 * tid]     + beta[2 * tid];
    float o1 = d1 * r * gamma[2 * tid + 1] + beta[2 * tid + 1];
    float2 oo; oo.x = o0; oo.y = o1;
    *(float2*)&x[base + 2 * tid] = oo;
    unsigned lo, hi = splitpack(o0, o1, lo);
    a_av_h[(long)m * HKP + tid] = hi;
    a_av_l[(long)m * HKP + tid] = lo;
}

// ---------------- host ----------------
static inline int ceildiv(int a, int b) { return (a + b - 1) / b; }

extern "C" void kernel_launch(void* const* d_in, const int* in_sizes, int n_in,
                              void* d_out, int out_size) {
    const float* encoded   = (const float*)d_in[0];
    const float* true_val  = (const float*)d_in[1];
    const float* W_shift   = (const float*)d_in[2];
    const float* b_shift   = (const float*)d_in[3];
    const float* W_key     = (const float*)d_in[4];
    const float* b_key     = (const float*)d_in[5];
    const float* W_val     = (const float*)d_in[6];
    const float* b_val     = (const float*)d_in[7];
    const float* ln1_s     = (const float*)d_in[8];
    const float* ln1_b     = (const float*)d_in[9];
    const float* ff_w1     = (const float*)d_in[10];
    const float* ff_b1     = (const float*)d_in[11];
    const float* ff_w2     = (const float*)d_in[12];
    const float* ff_b2     = (const float*)d_in[13];
    const float* ln2_s     = (const float*)d_in[14];
    const float* ln2_b     = (const float*)d_in[15];
    const float* s_w_in    = (const float*)d_in[16];
    const float* s_b_in    = (const float*)d_in[17];
    const float* s_w_hid   = (const float*)d_in[18];
    const float* s_b_hid   = (const float*)d_in[19];
    const float* s_w_out   = (const float*)d_in[20];
    const float* s_b_out   = (const float*)d_in[21];
    const float* t_w_in    = (const float*)d_in[22];
    const float* t_b_in    = (const float*)d_in[23];
    const float* t_w_hid   = (const float*)d_in[24];
    const float* t_b_hid   = (const float*)d_in[25];
    const float* t_w_out   = (const float*)d_in[26];
    const float* t_b_out   = (const float*)d_in[27];
    const float* bn_lg     = (const float*)d_in[28];
    const float* bn_bt     = (const float*)d_in[29];

    // symbol addresses
    float *keys, *vals, *attval, *att;
    unsigned *evh, *evl, *aih, *ail, *avh, *avl;
    unsigned *h1h, *h1l, *h2h, *h2l, *h3h, *h3l, *h4h, *h4l, *inh, *inl;
    unsigned *wshh, *wshl, *wf1h, *wf1l, *wf2h, *wf2l, *winh, *winl, *whdh, *whdl, *wkvh, *wkvl;
    cudaGetSymbolAddress((void**)&keys,   g_keys);
    cudaGetSymbolAddress((void**)&vals,   g_vals);
    cudaGetSymbolAddress((void**)&attval, g_attval);
    cudaGetSymbolAddress((void**)&att,    g_att);
    cudaGetSymbolAddress((void**)&evh, a_ev_h);  cudaGetSymbolAddress((void**)&evl, a_ev_l);
    cudaGetSymbolAddress((void**)&aih, a_ai_h);  cudaGetSymbolAddress((void**)&ail, a_ai_l);
    cudaGetSymbolAddress((void**)&avh, a_av_h);  cudaGetSymbolAddress((void**)&avl, a_av_l);
    cudaGetSymbolAddress((void**)&h1h, a_h1h);   cudaGetSymbolAddress((void**)&h1l, a_h1l);
    cudaGetSymbolAddress((void**)&h2h, a_h2h);   cudaGetSymbolAddress((void**)&h2l, a_h2l);
    cudaGetSymbolAddress((void**)&h3h, a_h3h);   cudaGetSymbolAddress((void**)&h3l, a_h3l);
    cudaGetSymbolAddress((void**)&h4h, a_h4h);   cudaGetSymbolAddress((void**)&h4l, a_h4l);
    cudaGetSymbolAddress((void**)&inh, a_inh);   cudaGetSymbolAddress((void**)&inl, a_inl);
    cudaGetSymbolAddress((void**)&wshh, w_sh_h); cudaGetSymbolAddress((void**)&wshl, w_sh_l);
    cudaGetSymbolAddress((void**)&wf1h, w_f1_h); cudaGetSymbolAddress((void**)&wf1l, w_f1_l);
    cudaGetSymbolAddress((void**)&wf2h, w_f2_h); cudaGetSymbolAddress((void**)&wf2l, w_f2_l);
    cudaGetSymbolAddress((void**)&winh, w_in_h); cudaGetSymbolAddress((void**)&winl, w_in_l);
    cudaGetSymbolAddress((void**)&whdh, w_hd_h); cudaGetSymbolAddress((void**)&whdl, w_hd_l);
    cudaGetSymbolAddress((void**)&wkvh, w_kv_h); cudaGetSymbolAddress((void**)&wkvl, w_kv_l);

    cudaFuncSetAttribute(k_mma<0,0>, cudaFuncAttributeMaxDynamicSharedMemorySize, SMEMSZ);
    cudaFuncSetAttribute(k_mma<1,1>, cudaFuncAttributeMaxDynamicSharedMemorySize, SMEMSZ);
    cudaFuncSetAttribute(k_mma<2,1>, cudaFuncAttributeMaxDynamicSharedMemorySize, SMEMSZ);

    // ---- weight preconversion ----
    {
        k_convw<<<dim3(ceildiv(AIKP*HDIM,256),1,1), 256>>>(W_shift, wshh, wshl, VV*CC, HDIM, AIKP);
        k_convw<<<dim3(ceildiv(HKP*HDIM,256),1,LLAY), 256>>>(ff_w1, wf1h, wf1l, HDIM, HDIM, HKP);
        k_convw<<<dim3(ceildiv(HKP*HDIM,256),1,LLAY), 256>>>(ff_w2, wf2h, wf2l, HDIM, HDIM, HKP);
        long inoff = (long)NB_*INKP*HDIM;
        k_convw<<<dim3(ceildiv(INKP*HDIM,256),1,NB_), 256>>>(s_w_in, winh, winl, HDIM+VV, HDIM, INKP);
        k_convw<<<dim3(ceildiv(INKP*HDIM,256),1,NB_), 256>>>(t_w_in, winh+inoff, winl+inoff, HDIM+VV, HDIM, INKP);
        long hdoff = (long)NB_*NHID_*HKP*HDIM;
        k_convw<<<dim3(ceildiv(HKP*HDIM,256),1,NB_*NHID_), 256>>>(s_w_hid, whdh, whdl, HDIM, HDIM, HKP);
        k_convw<<<dim3(ceildiv(HKP*HDIM,256),1,NB_*NHID_), 256>>>(t_w_hid, whdh+hdoff, whdl+hdoff, HDIM, HDIM, HKP);
        long kvoff = (long)LLAY*HH*EVKP*DD;
        k_convw<<<dim3(ceildiv(EVKP*DD,256),1,LLAY*HH), 256>>>(W_key, wkvh, wkvl, DIN_, DD, EVKP);
        k_convw<<<dim3(ceildiv(EVKP*DD,256),1,LLAY*HH), 256>>>(W_val, wkvh+kvoff, wkvl+kvoff, DIN_, DD, EVKP);
    }

    // ---- builders ----
    k_build_ev<<<(int)(((long)MKV*EVKP + 255)/256), 256>>>(encoded, true_val);
    k_build_attin<<<(int)(((long)MQ*AIKP + 255)/256), 256>>>(encoded);

    // ---- K/V projections: fused 64 z-slices ----
    {
        long kvoff = (long)LLAY*HH*EVKP*DD;
        dim3 g(1, ceildiv(MKV, BM), 2*LLAY*HH);
        k_mma<0,0><<<g, 256, SMEMSZ>>>(evh, evl, wkvh, wkvl, b_key, keys, 0, 0,
                                       evh, evl, wkvh+kvoff, wkvl+kvoff, b_val, vals, 0, 0,
                                       MKV, DD, EVKP, LLAY*HH,
                                       (long)EVKP*DD, (long)DD, (long)MKV*DD);
    }

    // ---- shift ----
    {
        dim3 g(HDIM/BN, ceildiv(MQ, BM), 1);
        k_mma<0,0><<<g, 256, SMEMSZ>>>(aih, ail, wshh, wshl, b_shift, attval, 0, 0,
                                       aih, ail, wshh, wshl, b_shift, attval, 0, 0,
                                       MQ, HDIM, AIKP, 1, 0L, 0L, 0L);
    }

    // ---- transformer layers ----
    for (int l = 0; l < LLAY; l++) {
        k_attn2<<<BNN*HH, 128>>>(keys, vals, l);
        k_add_ln<<<MQ, 256>>>(attval, att, ln1_s + (long)l*HDIM, ln1_b + (long)l*HDIM);
        dim3 g(HDIM/BN, ceildiv(MQ, BM), 1);
        k_mma<1,1><<<g, 256, SMEMSZ>>>(avh, avl, wf1h + (long)l*HKP*HDIM, wf1l + (long)l*HKP*HDIM,
                                       ff_b1 + (long)l*HDIM, 0, h1h, h1l,
                                       avh, avl, wf1h + (long)l*HKP*HDIM, wf1l + (long)l*HKP*HDIM,
                                       ff_b1 + (long)l*HDIM, 0, h1h, h1l,
                                       MQ, HDIM, HKP, 1, 0L, 0L, 0L);
        k_mma<0,0><<<g, 256, SMEMSZ>>>(h1h, h1l, wf2h + (long)l*HKP*HDIM, wf2l + (long)l*HKP*HDIM,
                                       ff_b2 + (long)l*HDIM, att, 0, 0,
                                       h1h, h1l, wf2h + (long)l*HKP*HDIM, wf2l + (long)l*HKP*HDIM,
                                       ff_b2 + (long)l*HDIM, att, 0, 0,
                                       MQ, HDIM, HKP, 1, 0L, 0L, 0L);
        k_add_ln<<<MQ, 256>>>(attval, att, ln2_s + (long)l*HDIM, ln2_b + (long)l*HDIM);
    }

    // ---- RealNVP flow ----
    k_build_inp_y<<<(int)(((long)MQ*INKP + 255)/256), 256>>>();
    k_init_u_mu<<<ceildiv(MQ, 256), 256>>>(true_val);

    dim3 gd(HDIM/BN, ceildiv(MQ, BM), 2);
    long inoff = (long)NB_*INKP*HDIM;
    long hdoff = (long)NB_*NHID_*HKP*HDIM;

    for (int blk = 0; blk < NB_; blk++) {
        // in-layer: s->tanh planes h1, t->relu planes h3
        k_mma<2,1><<<gd, 256, SMEMSZ>>>(inh, inl, winh + (long)blk*INKP*HDIM, winl + (long)blk*INKP*HDIM,
                                        s_b_in + (long)blk*HDIM, 0, h1h, h1l,
                                        inh, inl, winh + inoff + (long)blk*INKP*HDIM, winl + inoff + (long)blk*INKP*HDIM,
                                        t_b_in + (long)blk*HDIM, 0, h3h, h3l,
                                        MQ, HDIM, INKP, 1, 0L, 0L, 0L);
        unsigned *csh = h1h, *csl = h1l, *nsh = h2h, *nsl = h2l;
        unsigned *cth = h3h, *ctl = h3l, *nth = h4h, *ntl = h4l;
        for (int i = 0; i < NHID_; i++) {
            long wo = ((long)blk*NHID_ + i)*HKP*HDIM;
            k_mma<2,1><<<gd, 256, SMEMSZ>>>(csh, csl, whdh + wo, whdl + wo,
                                            s_b_hid + ((long)blk*NHID_ + i)*HDIM, 0, nsh, nsl,
                                            cth, ctl, whdh + hdoff + wo, whdl + hdoff + wo,
                                            t_b_hid + ((long)blk*NHID_ + i)*HDIM, 0, nth, ntl,
                                            MQ, HDIM, HKP, 1, 0L, 0L, 0L);
            unsigned* t;
            t = csh; csh = nsh; nsh = t;  t = csl; csl = nsl; nsl = t;
            t = cth; cth = nth; nth = t;  t = ctl; ctl = ntl; ntl = t;
        }
        k_outrow<<<(2*MQ)/8, 256>>>(csh, csl, cth, ctl,
                                    s_w_out + (long)blk*HDIM*VV, s_b_out + (long)blk*VV,
                                    t_w_out + (long)blk*HDIM*VV, t_b_out + (long)blk*VV);
        k_coupling_stats<<<T2_*VV, 256>>>(blk);
        k_bn_apply_mu<<<ceildiv(MQ, 256), 256>>>(bn_lg + (long)blk*VV, bn_bt + (long)blk*VV, blk);
    }

    // ---- final NLL ----
    k_final<<<ceildiv(BNN, 256), 256>>>((float*)d_out);
}

// round 6
// speedup vs baseline: 3.3537x; 1.0041x over previous
#include <cuda_runtime.h>
#include <cuda_bf16.h>
#include <math.h>
#include <stdint.h>

// ---------------- problem dims ----------------
#define NV_   975
#define TT    48
#define T2_   12
#define CC    128
#define VV    3
#define HH    8
#define DD    64
#define HDIM  512
#define LLAY  4
#define NB_   6
#define NHID_ 4
#define DIN_  387
#define NVG   325
#define BNN   650
#define MKV   (BNN*TT)   // 31200
#define MQ    (BNN*T2_)  // 7800
#define LOG2PI_F 1.8378770664093453f

// k-pair counts (multiples of 16)
#define EVKP 208   // ceil(387/2) -> 208
#define AIKP 192   // 384/2
#define HKP  256   // 512/2
#define INKP 272   // ceil(515/2)=258 -> 272

#define NKV  2048  // 32 (l,h) slices x 64

// ---------------- fp32 scratch ----------------
__device__ float g_keys[LLAY*HH*MKV*DD];
__device__ float g_vals[LLAY*HH*MKV*DD];
__device__ float g_attval[MQ*HDIM];
__device__ float g_att[MQ*HDIM];
__device__ float g_s[MQ*VV];
__device__ float g_t[MQ*VV];
__device__ float g_u[MQ*VV];
__device__ float g_ld[MQ*VV];
__device__ float g_bnstats[T2_*VV*2];

// ---------------- packed bf16 hi/lo activation planes (A: [M][KP2]) ----------------
__device__ __align__(128) unsigned a_ev_h[MKV*EVKP], a_ev_l[MKV*EVKP];
__device__ __align__(128) unsigned a_ai_h[MQ*AIKP],  a_ai_l[MQ*AIKP];
__device__ __align__(128) unsigned a_av_h[MQ*HKP],   a_av_l[MQ*HKP];
__device__ __align__(128) unsigned a_h1h[MQ*HKP], a_h1l[MQ*HKP];
__device__ __align__(128) unsigned a_h2h[MQ*HKP], a_h2l[MQ*HKP];
__device__ __align__(128) unsigned a_h3h[MQ*HKP], a_h3l[MQ*HKP];
__device__ __align__(128) unsigned a_h4h[MQ*HKP], a_h4l[MQ*HKP];
__device__ __align__(128) unsigned a_inh[MQ*INKP], a_inl[MQ*INKP];

// ---------------- transposed weight planes (B: [N][KP2], K-major rows) ----------------
__device__ __align__(128) unsigned w_shT_h[HDIM*AIKP], w_shT_l[HDIM*AIKP];
__device__ __align__(128) unsigned w_f1T_h[LLAY*HDIM*HKP], w_f1T_l[LLAY*HDIM*HKP];
__device__ __align__(128) unsigned w_f2T_h[LLAY*HDIM*HKP], w_f2T_l[LLAY*HDIM*HKP];
__device__ __align__(128) unsigned w_inT_h[2*NB_*HDIM*INKP], w_inT_l[2*NB_*HDIM*INKP];
__device__ __align__(128) unsigned w_hdT_h[2*NB_*NHID_*HDIM*HKP], w_hdT_l[2*NB_*NHID_*HDIM*HKP];
__device__ __align__(128) unsigned w_kvT_h[2*NKV*EVKP], w_kvT_l[2*NKV*EVKP];

// ---------------- helpers ----------------
__device__ __forceinline__ unsigned splitpack(float x0, float x1, unsigned& lo) {
    __nv_bfloat16 h0 = __float2bfloat16_rn(x0);
    __nv_bfloat16 h1 = __float2bfloat16_rn(x1);
    float r0 = x0 - __bfloat162float(h0);
    float r1 = x1 - __bfloat162float(h1);
    __nv_bfloat162 hp = __halves2bfloat162(h0, h1);
    __nv_bfloat162 lp = __halves2bfloat162(__float2bfloat16_rn(r0), __float2bfloat16_rn(r1));
    lo = *reinterpret_cast<unsigned*>(&lp);
    return *reinterpret_cast<unsigned*>(&hp);
}

__device__ __forceinline__ float2 unpack2(unsigned h, unsigned l) {
    __nv_bfloat162 hb = *reinterpret_cast<__nv_bfloat162*>(&h);
    __nv_bfloat162 lb = *reinterpret_cast<__nv_bfloat162*>(&l);
    float2 r;
    r.x = __bfloat162float(hb.x) + __bfloat162float(lb.x);
    r.y = __bfloat162float(hb.y) + __bfloat162float(lb.y);
    return r;
}

__device__ __forceinline__ void cpa16s(unsigned saddr, const void* gsrc) {
    asm volatile("cp.async.cg.shared.global [%0], [%1], 16;" :: "r"(saddr), "l"(gsrc));
}

__device__ __forceinline__ void mma16(float* c, const unsigned* a, const unsigned* b) {
    asm volatile(
        "mma.sync.aligned.m16n8k16.row.col.f32.bf16.bf16.f32 "
        "{%0,%1,%2,%3}, {%4,%5,%6,%7}, {%8,%9}, {%0,%1,%2,%3};"
        : "+f"(c[0]), "+f"(c[1]), "+f"(c[2]), "+f"(c[3])
        : "r"(a[0]), "r"(a[1]), "r"(a[2]), "r"(a[3]), "r"(b[0]), "r"(b[1]));
}

template <int A> __device__ __forceinline__ float actf(float v) {
    if (A == 1) return fmaxf(v, 0.f);
    if (A == 2) return tanhf(v);
    return v;
}

// ---------------- weight pre-conversion (transposed: [Z][K][N] -> [Z][N][KP2]) ----------------
__global__ void k_convwT(const float* __restrict__ src, unsigned* __restrict__ dhi,
                         unsigned* __restrict__ dlo, int K, int N, int KP2) {
    long z = blockIdx.z;
    src += z * (long)K * N;
    dhi += z * (long)N * KP2;
    dlo += z * (long)N * KP2;
    int idx = blockIdx.x * 256 + threadIdx.x;
    if (idx >= N * KP2) return;
    int n = idx / KP2, kp = idx - n * KP2;
    float x0 = (2 * kp     < K) ? src[(long)(2 * kp) * N + n]     : 0.f;
    float x1 = (2 * kp + 1 < K) ? src[(long)(2 * kp + 1) * N + n] : 0.f;
    unsigned lo, hi = splitpack(x0, x1, lo);
    dhi[idx] = hi; dlo[idx] = lo;
}

// ---------------- builders ----------------
__global__ void k_build_ev(const float* __restrict__ enc, const float* __restrict__ tv) {
    long idx = (long)blockIdx.x * 256 + threadIdx.x;
    if (idx >= (long)MKV * EVKP) return;
    int kp = (int)(idx % EVKP);
    int m  = (int)(idx / EVKP);
    int b = m / TT, tt = m % TT;
    int ob = b / NVG, nvb = (b % NVG) * VV;
    float x[2];
#pragma unroll
    for (int t = 0; t < 2; t++) {
        int e = 2 * kp + t;
        float v = 0.f;
        if (e < DIN_) {
            int vv = e / (CC + 1), cc = e % (CC + 1);
            int nv = nvb + vv;
            if (cc < CC) v = enc[(((long)ob * NV_ + nv) * TT + tt) * CC + cc];
            else         v = tv[((long)ob * NV_ + nv) * TT + tt];
        }
        x[t] = v;
    }
    unsigned lo, hi = splitpack(x[0], x[1], lo);
    a_ev_h[idx] = hi; a_ev_l[idx] = lo;
}

__global__ void k_build_attin(const float* __restrict__ enc) {
    long idx = (long)blockIdx.x * 256 + threadIdx.x;
    if (idx >= (long)MQ * AIKP) return;
    int kp = (int)(idx % AIKP);
    int m  = (int)(idx / AIKP);
    int b = m / T2_, q = m % T2_;
    int ob = b / NVG, nvb = (b % NVG) * VV;
    float x[2];
#pragma unroll
    for (int t = 0; t < 2; t++) {
        int e = 2 * kp + t;
        int vv = e / CC, cc = e % CC;
        x[t] = enc[(((long)ob * NV_ + nvb + vv) * TT + (TT - T2_) + q) * CC + cc];
    }
    unsigned lo, hi = splitpack(x[0], x[1], lo);
    a_ai_h[idx] = hi; a_ai_l[idx] = lo;
}

__global__ void k_build_inp_y() {
    long idx = (long)blockIdx.x * 256 + threadIdx.x;
    if (idx >= (long)MQ * INKP) return;
    int kp = (int)(idx % INKP);
    int m  = (int)(idx / INKP);
    if (kp < HKP) {
        a_inh[idx] = a_av_h[(long)m * HKP + kp];
        a_inl[idx] = a_av_l[(long)m * HKP + kp];
    } else if (kp >= 258) {
        a_inh[idx] = 0u; a_inl[idx] = 0u;
    }
}

__global__ void k_init_u_mu(const float* __restrict__ tv) {
    int m = blockIdx.x * 256 + threadIdx.x;
    if (m >= MQ) return;
    int b = m / T2_, q = m % T2_;
    int ob = b / NVG, nvb = (b % NVG) * VV;
    float u[3];
#pragma unroll
    for (int v = 0; v < 3; v++) {
        u[v] = tv[((long)ob * NV_ + nvb + v) * TT + (TT - T2_) + q];
        g_u[m * 3 + v] = u[v];
        g_ld[m * 3 + v] = 0.f;
    }
    unsigned lo, hi;
    hi = splitpack(0.f, u[1], lo);
    a_inh[(long)m * INKP + 256] = hi; a_inl[(long)m * INKP + 256] = lo;
    hi = splitpack(0.f, 0.f, lo);
    a_inh[(long)m * INKP + 257] = hi; a_inl[(long)m * INKP + 257] = lo;
}

__global__ void k_coupling_stats(int blk) {
    int col = blockIdx.x;
    int v   = col % VV;
    int mask = (v + blk) & 1;
    int tid = threadIdx.x;
    __shared__ float rs[256], rq[256];
    float s = 0.f, q = 0.f;
    for (int b = tid; b < BNN; b += 256) {
        int e = b * (T2_ * VV) + col;
        float u = g_u[e];
        if (!mask) {
            float sv = g_s[e];
            u = (u - g_t[e]) * expf(-sv);
            g_u[e] = u;
            g_ld[e] -= sv;
        }
        s += u; q += u * u;
    }
    rs[tid] = s; rq[tid] = q;
    __syncthreads();
    for (int st = 128; st > 0; st >>= 1) {
        if (tid < st) { rs[tid] += rs[tid + st]; rq[tid] += rq[tid + st]; }
        __syncthreads();
    }
    if (tid == 0) {
        float mean = rs[0] / (float)BNN;
        float var  = rq[0] / (float)BNN - mean * mean;
        g_bnstats[col * 2 + 0] = mean;
        g_bnstats[col * 2 + 1] = var;
    }
}

__global__ void k_bn_apply_mu(const float* __restrict__ lgam, const float* __restrict__ beta, int blk) {
    int m = blockIdx.x * 256 + threadIdx.x;
    if (m >= MQ) return;
    int t2 = m % T2_;
    float mu[3];
#pragma unroll
    for (int v = 0; v < 3; v++) {
        int col = t2 * 3 + v;
        float mean = g_bnstats[col * 2 + 0];
        float var  = g_bnstats[col * 2 + 1];
        float lg = lgam[v], bt = beta[v];
        float u = expf(lg) * (g_u[m * 3 + v] - mean) * rsqrtf(var + 1e-5f) + bt;
        g_u[m * 3 + v] = u;
        g_ld[m * 3 + v] += lg - 0.5f * logf(var + 1e-5f);
        int nmask = (v + blk + 1) & 1;
        mu[v] = nmask ? u : 0.f;
    }
    if (blk < NB_ - 1) {
        unsigned lo, hi;
        hi = splitpack(mu[0], mu[1], lo);
        a_inh[(long)m * INKP + 256] = hi; a_inl[(long)m * INKP + 256] = lo;
        hi = splitpack(mu[2], 0.f, lo);
        a_inh[(long)m * INKP + 257] = hi; a_inl[(long)m * INKP + 257] = lo;
    }
}

__global__ void k_final(float* __restrict__ out) {
    int b = blockIdx.x * 256 + threadIdx.x;
    if (b >= BNN) return;
    float acc = 0.f;
    for (int i = 0; i < T2_ * VV; i++) {
        float u = g_u[b * (T2_ * VV) + i];
        acc += 0.5f * u * u + 0.5f * LOG2PI_F - g_ld[b * (T2_ * VV) + i];
    }
    out[b] = acc;
}

// ---------------- bf16x3 HMMA GEMM, 128x128 block tile ----------------
// smem: [stage][Ah|Al|Bh|Bl], each plane 128 rows x pitch 20 words; A/B rows = m/n, cols = kpairs.
// Warp tile 32(M) x 64(N): wm = wid&3, wn = wid>>2.
#define PITCH 20
#define PLW   (128*PITCH)          // words per plane = 2560
#define STW   (4*PLW)              // words per stage = 10240
#define GSMEM (2*STW*4)            // bytes = 81920

// CM: 0 = fp32 C row-major; 1 = packed planes Ph/Pl; 2 = KV scatter C[slice][m][64]
template <int ACT0, int ACT1, int CM>
__global__ void __launch_bounds__(256, 2)
k_mma(const unsigned* __restrict__ Ah0, const unsigned* __restrict__ Al0,
      const unsigned* __restrict__ Wh0, const unsigned* __restrict__ Wl0,
      const float* __restrict__ b0, float* __restrict__ C0,
      unsigned* __restrict__ Ph0, unsigned* __restrict__ Pl0,
      const unsigned* __restrict__ Ah1, const unsigned* __restrict__ Al1,
      const unsigned* __restrict__ Wh1, const unsigned* __restrict__ Wl1,
      const float* __restrict__ b1, float* __restrict__ C1,
      unsigned* __restrict__ Ph1, unsigned* __restrict__ Pl1,
      int M, int N, int KP2) {
    extern __shared__ __align__(16) unsigned dsm[];

    bool first = (blockIdx.z == 0);
    const unsigned* Ah = first ? Ah0 : Ah1;
    const unsigned* Al = first ? Al0 : Al1;
    const unsigned* Wh = first ? Wh0 : Wh1;
    const unsigned* Wl = first ? Wl0 : Wl1;
    const float* bias  = first ? b0 : b1;
    float* C           = first ? C0 : C1;
    unsigned* Ph       = first ? Ph0 : Ph1;
    unsigned* Pl       = first ? Pl0 : Pl1;

    int tile_m = blockIdx.y * 128;
    int tile_n = blockIdx.x * 128;
    int tid = threadIdx.x, lane = tid & 31, wid = tid >> 5;
    int grp = lane >> 2, tig = lane & 3;
    int wm = wid & 3, wn = wid >> 2;
    unsigned sbb = (unsigned)__cvta_generic_to_shared(dsm);

    float acc[2][8][4];
#pragma unroll
    for (int i = 0; i < 2; i++)
#pragma unroll
        for (int j = 0; j < 8; j++)
#pragma unroll
            for (int e = 0; e < 4; e++) acc[i][j][e] = 0.f;

    auto load_stage = [&](int st, int kp0) {
        unsigned base = (unsigned)st * STW;
        // A: 2 planes x 128 rows x 4 chunks(16B = 4 kp)
#pragma unroll
        for (int t = 0; t < 4; t++) {
            int idx = tid + t * 256;
            int p = idx >> 9, r = (idx >> 2) & 127, c = idx & 3;
            int gm = tile_m + r; if (gm >= M) gm = M - 1;
            const unsigned* src = (p ? Al : Ah) + (long)gm * KP2 + kp0 + c * 4;
            cpa16s(sbb + (base + (unsigned)p * PLW + (unsigned)(r * PITCH + c * 4)) * 4u, src);
        }
        // B: 2 planes x 128 n-rows x 4 chunks
#pragma unroll
        for (int t = 0; t < 4; t++) {
            int idx = tid + t * 256;
            int p = idx >> 9, r = (idx >> 2) & 127, c = idx & 3;
            int gn = tile_n + r;
            const unsigned* src = (p ? Wl : Wh) + (long)gn * KP2 + kp0 + c * 4;
            cpa16s(sbb + (base + 2u * PLW + (unsigned)p * PLW + (unsigned)(r * PITCH + c * 4)) * 4u, src);
        }
        asm volatile("cp.async.commit_group;" ::: "memory");
    };

    int iters = KP2 / 16;
    load_stage(0, 0);

    for (int it = 0; it < iters; it++) {
        if (it + 1 < iters) {
            load_stage((it + 1) & 1, (it + 1) * 16);
            asm volatile("cp.async.wait_group 1;" ::: "memory");
        } else {
            asm volatile("cp.async.wait_group 0;" ::: "memory");
        }
        __syncthreads();

        unsigned base = (unsigned)(it & 1) * STW;
        const unsigned* SAh = dsm + base;
        const unsigned* SAl = dsm + base + PLW;
        const unsigned* SBh = dsm + base + 2 * PLW;
        const unsigned* SBl = dsm + base + 3 * PLW;

#pragma unroll
        for (int s2 = 0; s2 < 2; s2++) {
            int kb = s2 * 8;
            unsigned ah[2][4], al[2][4];
#pragma unroll
            for (int i = 0; i < 2; i++) {
                int rb = wm * 32 + i * 16 + grp;
                ah[i][0] = SAh[rb * PITCH + kb + tig];
                ah[i][1] = SAh[(rb + 8) * PITCH + kb + tig];
                ah[i][2] = SAh[rb * PITCH + kb + tig + 4];
                ah[i][3] = SAh[(rb + 8) * PITCH + kb + tig + 4];
                al[i][0] = SAl[rb * PITCH + kb + tig];
                al[i][1] = SAl[(rb + 8) * PITCH + kb + tig];
                al[i][2] = SAl[rb * PITCH + kb + tig + 4];
                al[i][3] = SAl[(rb + 8) * PITCH + kb + tig + 4];
            }
#pragma unroll
            for (int j = 0; j < 8; j++) {
                int nb = wn * 64 + j * 8 + grp;
                unsigned bh[2], bl[2];
                bh[0] = SBh[nb * PITCH + kb + tig];
                bh[1] = SBh[nb * PITCH + kb + tig + 4];
                bl[0] = SBl[nb * PITCH + kb + tig];
                bl[1] = SBl[nb * PITCH + kb + tig + 4];
#pragma unroll
                for (int i = 0; i < 2; i++) {
                    mma16(acc[i][j], ah[i], bh);
                    mma16(acc[i][j], al[i], bh);
                    mma16(acc[i][j], ah[i], bl);
                }
            }
        }
        __syncthreads();
    }

    // epilogue
    int np2 = N >> 1;
#pragma unroll
    for (int i = 0; i < 2; i++) {
        int row0 = tile_m + wm * 32 + i * 16 + grp;
        int row1 = row0 + 8;
#pragma unroll
        for (int j = 0; j < 8; j++) {
            int col = tile_n + wn * 64 + j * 8 + tig * 2;
            float b0v = bias[col], b1v = bias[col + 1];
            float v00 = acc[i][j][0] + b0v, v01 = acc[i][j][1] + b1v;
            float v10 = acc[i][j][2] + b0v, v11 = acc[i][j][3] + b1v;
            if (first) {
                v00 = actf<ACT0>(v00); v01 = actf<ACT0>(v01);
                v10 = actf<ACT0>(v10); v11 = actf<ACT0>(v11);
            } else {
                v00 = actf<ACT1>(v00); v01 = actf<ACT1>(v01);
                v10 = actf<ACT1>(v10); v11 = actf<ACT1>(v11);
            }
            if (CM == 2) {
                // one slice per (block,wn): slice = col>>6, in-slice col = col&63
                int slice = col >> 6, cis = col & 63;
                float* d0 = C + ((long)slice * M + row0) * 64 + cis;
                float* d1 = C + ((long)slice * M + row1) * 64 + cis;
                if (row0 < M) { d0[0] = v00; d0[1] = v01; }
                if (row1 < M) { d1[0] = v10; d1[1] = v11; }
            } else if (CM == 0) {
                if (row0 < M) { C[(long)row0 * N + col] = v00; C[(long)row0 * N + col + 1] = v01; }
                if (row1 < M) { C[(long)row1 * N + col] = v10; C[(long)row1 * N + col + 1] = v11; }
            } else {
                unsigned lo, hi;
                if (row0 < M) {
                    hi = splitpack(v00, v01, lo);
                    Ph[(long)row0 * np2 + (col >> 1)] = hi;
                    Pl[(long)row0 * np2 + (col >> 1)] = lo;
                }
                if (row1 < M) {
                    hi = splitpack(v10, v11, lo);
                    Ph[(long)row1 * np2 + (col >> 1)] = hi;
                    Pl[(long)row1 * np2 + (col >> 1)] = lo;
                }
            }
        }
    }
}

// ---------------- flow output layer (N=3), warp per row ----------------
__global__ void k_outrow(const unsigned* __restrict__ hsh, const unsigned* __restrict__ hsl,
                         const unsigned* __restrict__ hth, const unsigned* __restrict__ htl,
                         const float* __restrict__ sw, const float* __restrict__ sb,
                         const float* __restrict__ tw, const float* __restrict__ tb) {
    __shared__ float Ws[2][HDIM * VV];
    __shared__ float Wb[2][VV];
    int tid = threadIdx.x;
    for (int i = tid; i < HDIM * VV; i += 256) { Ws[0][i] = sw[i]; Ws[1][i] = tw[i]; }
    if (tid < VV) { Wb[0][tid] = sb[tid]; Wb[1][tid] = tb[tid]; }
    __syncthreads();

    int wi = blockIdx.x * 8 + (tid >> 5);
    int lane = tid & 31;
    int net = (wi >= MQ) ? 1 : 0;
    int r = net ? (wi - MQ) : wi;
    const unsigned* Hh = net ? hth : hsh;
    const unsigned* Hl = net ? htl : hsl;
    const float* Wn = Ws[net];
    float a0 = 0.f, a1 = 0.f, a2 = 0.f;
    for (int cp = lane; cp < HKP; cp += 32) {
        float2 v = unpack2(Hh[(long)r * HKP + cp], Hl[(long)r * HKP + cp]);
        int c0 = 2 * cp;
        a0 += v.x * Wn[c0 * 3 + 0] + v.y * Wn[(c0 + 1) * 3 + 0];
        a1 += v.x * Wn[c0 * 3 + 1] + v.y * Wn[(c0 + 1) * 3 + 1];
        a2 += v.x * Wn[c0 * 3 + 2] + v.y * Wn[(c0 + 1) * 3 + 2];
    }
#pragma unroll
    for (int o = 16; o; o >>= 1) {
        a0 += __shfl_xor_sync(0xffffffffu, a0, o);
        a1 += __shfl_xor_sync(0xffffffffu, a1, o);
        a2 += __shfl_xor_sync(0xffffffffu, a2, o);
    }
    if (lane == 0) {
        float* Cp = net ? g_t : g_s;
        Cp[r * 3 + 0] = a0 + Wb[net][0];
        Cp[r * 3 + 1] = a1 + Wb[net][1];
        Cp[r * 3 + 2] = a2 + Wb[net][2];
    }
}

// ---------------- attention ----------------
__global__ void k_attn2(const float* __restrict__ keys, const float* __restrict__ vals, int l) {
    int h = blockIdx.x & 7, b = blockIdx.x >> 3;
    int tid = threadIdx.x, lane = tid & 31, wq = tid >> 5;
    __shared__ float KsT[DD * TT];
    __shared__ float Vs[TT * DD];
    __shared__ float Qs[T2_ * DD];
    __shared__ float Ps[4][64];

    long base = ((long)(l * HH + h) * MKV + (long)b * TT) * DD;
    const float4* k4 = (const float4*)(keys + base);
    const float4* v4 = (const float4*)(vals + base);
    for (int i = tid; i < TT * DD / 4; i += 128) {
        float4 kv = k4[i];
        int w = i >> 4, d = (i & 15) << 2;
        KsT[(d + 0) * TT + w] = kv.x;
        KsT[(d + 1) * TT + w] = kv.y;
        KsT[(d + 2) * TT + w] = kv.z;
        KsT[(d + 3) * TT + w] = kv.w;
        ((float4*)Vs)[i] = v4[i];
    }
    for (int i = tid; i < T2_ * DD / 4; i += 128) {
        int q = i >> 4, d4 = (i & 15);
        ((float4*)Qs)[i] = *(const float4*)(g_attval + (long)(b * T2_ + q) * HDIM + h * DD + d4 * 4);
    }
    __syncthreads();

#pragma unroll
    for (int qi = 0; qi < 3; qi++) {
        int q = wq + qi * 4;
        int lim = (TT - T2_) + q;
        float d0 = 0.f, d1 = 0.f;
        const float* qrow = Qs + q * DD;
#pragma unroll
        for (int d = 0; d < DD; d++) {
            float qd = qrow[d];
            d0 += qd * KsT[d * TT + lane];
            d1 += qd * KsT[d * TT + ((lane + 32) & 63)];
        }
        float s0 = (lane < lim) ? d0 * 0.125f : -1e30f;
        float s1 = (lane + 32 < lim) ? d1 * 0.125f : -1e30f;
        float mx = fmaxf(s0, s1);
#pragma unroll
        for (int o = 16; o; o >>= 1) mx = fmaxf(mx, __shfl_xor_sync(0xffffffffu, mx, o));
        float e0 = (lane < lim) ? expf(s0 - mx) : 0.f;
        float e1 = (lane + 32 < lim) ? expf(s1 - mx) : 0.f;
        float sm = e0 + e1;
#pragma unroll
        for (int o = 16; o; o >>= 1) sm += __shfl_xor_sync(0xffffffffu, sm, o);
        Ps[wq][lane] = e0;
        Ps[wq][lane + 32] = e1;
        __syncwarp();
        float inv = 1.f / sm;
        float o0 = 0.f, o1 = 0.f;
        for (int w2 = 0; w2 < lim; w2++) {
            float p = Ps[wq][w2];
            o0 += p * Vs[w2 * DD + lane];
            o1 += p * Vs[w2 * DD + lane + 32];
        }
        long orow = (long)(b * T2_ + q) * HDIM + h * DD;
        g_att[orow + lane] = o0 * inv;
        g_att[orow + lane + 32] = o1 * inv;
        __syncwarp();
    }
}

// ---------------- add + layernorm; emits fp32 + packed planes ----------------
__global__ void k_add_ln(float* __restrict__ x, const float* __restrict__ y,
                         const float* __restrict__ gamma, const float* __restrict__ beta) {
    int m = blockIdx.x;
    int tid = threadIdx.x;
    long base = (long)m * HDIM;
    float2 xx = *(const float2*)&x[base + 2 * tid];
    float2 yy = *(const float2*)&y[base + 2 * tid];
    float v0 = xx.x + yy.x, v1 = xx.y + yy.y;
    __shared__ float red[256];
    __shared__ float s_mean, s_rstd;
    red[tid] = v0 + v1;
    __syncthreads();
    for (int st = 128; st > 0; st >>= 1) {
        if (tid < st) red[tid] += red[tid + st];
        __syncthreads();
    }
    if (tid == 0) s_mean = red[0] / (float)HDIM;
    __syncthreads();
    float mn = s_mean;
    float d0 = v0 - mn, d1 = v1 - mn;
    red[tid] = d0 * d0 + d1 * d1;
    __syncthreads();
    for (int st = 128; st > 0; st >>= 1) {
        if (tid < st) red[tid] += red[tid + st];
        __syncthreads();
    }
    if (tid == 0) s_rstd = rsqrtf(red[0] / (float)HDIM + 1e-5f);
    __syncthreads();
    float r = s_rstd;
    float o0 = d0 * r * gamma[2 * tid]     + beta[2 * tid];
    float o1 = d1 * r * gamma[2 * tid + 1] + beta[2 * tid + 1];
    float2 oo; oo.x = o0; oo.y = o1;
    *(float2*)&x[base + 2 * tid] = oo;
    unsigned lo, hi = splitpack(o0, o1, lo);
    a_av_h[(long)m * HKP + tid] = hi;
    a_av_l[(long)m * HKP + tid] = lo;
}

// ---------------- host ----------------
static inline int ceildiv(int a, int b) { return (a + b - 1) / b; }

extern "C" void kernel_launch(void* const* d_in, const int* in_sizes, int n_in,
                              void* d_out, int out_size) {
    const float* encoded   = (const float*)d_in[0];
    const float* true_val  = (const float*)d_in[1];
    const float* W_shift   = (const float*)d_in[2];
    const float* b_shift   = (const float*)d_in[3];
    const float* W_key     = (const float*)d_in[4];
    const float* b_key     = (const float*)d_in[5];
    const float* W_val     = (const float*)d_in[6];
    const float* b_val     = (const float*)d_in[7];
    const float* ln1_s     = (const float*)d_in[8];
    const float* ln1_b     = (const float*)d_in[9];
    const float* ff_w1     = (const float*)d_in[10];
    const float* ff_b1     = (const float*)d_in[11];
    const float* ff_w2     = (const float*)d_in[12];
    const float* ff_b2     = (const float*)d_in[13];
    const float* ln2_s     = (const float*)d_in[14];
    const float* ln2_b     = (const float*)d_in[15];
    const float* s_w_in    = (const float*)d_in[16];
    const float* s_b_in    = (const float*)d_in[17];
    const float* s_w_hid   = (const float*)d_in[18];
    const float* s_b_hid   = (const float*)d_in[19];
    const float* s_w_out   = (const float*)d_in[20];
    const float* s_b_out   = (const float*)d_in[21];
    const float* t_w_in    = (const float*)d_in[22];
    const float* t_b_in    = (const float*)d_in[23];
    const float* t_w_hid   = (const float*)d_in[24];
    const float* t_b_hid   = (const float*)d_in[25];
    const float* t_w_out   = (const float*)d_in[26];
    const float* t_b_out   = (const float*)d_in[27];
    const float* bn_lg     = (const float*)d_in[28];
    const float* bn_bt     = (const float*)d_in[29];

    float *keys, *vals, *attval, *att;
    unsigned *evh, *evl, *aih, *ail, *avh, *avl;
    unsigned *h1h, *h1l, *h2h, *h2l, *h3h, *h3l, *h4h, *h4l, *inh, *inl;
    unsigned *wshh, *wshl, *wf1h, *wf1l, *wf2h, *wf2l, *winh, *winl, *whdh, *whdl, *wkvh, *wkvl;
    cudaGetSymbolAddress((void**)&keys,   g_keys);
    cudaGetSymbolAddress((void**)&vals,   g_vals);
    cudaGetSymbolAddress((void**)&attval, g_attval);
    cudaGetSymbolAddress((void**)&att,    g_att);
    cudaGetSymbolAddress((void**)&evh, a_ev_h);  cudaGetSymbolAddress((void**)&evl, a_ev_l);
    cudaGetSymbolAddress((void**)&aih, a_ai_h);  cudaGetSymbolAddress((void**)&ail, a_ai_l);
    cudaGetSymbolAddress((void**)&avh, a_av_h);  cudaGetSymbolAddress((void**)&avl, a_av_l);
    cudaGetSymbolAddress((void**)&h1h, a_h1h);   cudaGetSymbolAddress((void**)&h1l, a_h1l);
    cudaGetSymbolAddress((void**)&h2h, a_h2h);   cudaGetSymbolAddress((void**)&h2l, a_h2l);
    cudaGetSymbolAddress((void**)&h3h, a_h3h);   cudaGetSymbolAddress((void**)&h3l, a_h3l);
    cudaGetSymbolAddress((void**)&h4h, a_h4h);   cudaGetSymbolAddress((void**)&h4l, a_h4l);
    cudaGetSymbolAddress((void**)&inh, a_inh);   cudaGetSymbolAddress((void**)&inl, a_inl);
    cudaGetSymbolAddress((void**)&wshh, w_shT_h); cudaGetSymbolAddress((void**)&wshl, w_shT_l);
    cudaGetSymbolAddress((void**)&wf1h, w_f1T_h); cudaGetSymbolAddress((void**)&wf1l, w_f1T_l);
    cudaGetSymbolAddress((void**)&wf2h, w_f2T_h); cudaGetSymbolAddress((void**)&wf2l, w_f2T_l);
    cudaGetSymbolAddress((void**)&winh, w_inT_h); cudaGetSymbolAddress((void**)&winl, w_inT_l);
    cudaGetSymbolAddress((void**)&whdh, w_hdT_h); cudaGetSymbolAddress((void**)&whdl, w_hdT_l);
    cudaGetSymbolAddress((void**)&wkvh, w_kvT_h); cudaGetSymbolAddress((void**)&wkvl, w_kvT_l);

    cudaFuncSetAttribute(k_mma<0,0,0>, cudaFuncAttributeMaxDynamicSharedMemorySize, GSMEM);
    cudaFuncSetAttribute(k_mma<0,0,2>, cudaFuncAttributeMaxDynamicSharedMemorySize, GSMEM);
    cudaFuncSetAttribute(k_mma<1,1,1>, cudaFuncAttributeMaxDynamicSharedMemorySize, GSMEM);
    cudaFuncSetAttribute(k_mma<2,1,1>, cudaFuncAttributeMaxDynamicSharedMemorySize, GSMEM);

    // ---- weight preconversion (transposed planes) ----
    long kvoff = (long)NKV * EVKP;
    long inoff = (long)NB_ * HDIM * INKP;
    long hdoff = (long)NB_ * NHID_ * HDIM * HKP;
    k_convwT<<<dim3(ceildiv(HDIM*AIKP,256),1,1), 256>>>(W_shift, wshh, wshl, VV*CC, HDIM, AIKP);
    k_convwT<<<dim3(ceildiv(HDIM*HKP,256),1,LLAY), 256>>>(ff_w1, wf1h, wf1l, HDIM, HDIM, HKP);
    k_convwT<<<dim3(ceildiv(HDIM*HKP,256),1,LLAY), 256>>>(ff_w2, wf2h, wf2l, HDIM, HDIM, HKP);
    k_convwT<<<dim3(ceildiv(HDIM*INKP,256),1,NB_), 256>>>(s_w_in, winh, winl, HDIM+VV, HDIM, INKP);
    k_convwT<<<dim3(ceildiv(HDIM*INKP,256),1,NB_), 256>>>(t_w_in, winh+inoff, winl+inoff, HDIM+VV, HDIM, INKP);
    k_convwT<<<dim3(ceildiv(HDIM*HKP,256),1,NB_*NHID_), 256>>>(s_w_hid, whdh, whdl, HDIM, HDIM, HKP);
    k_convwT<<<dim3(ceildiv(HDIM*HKP,256),1,NB_*NHID_), 256>>>(t_w_hid, whdh+hdoff, whdl+hdoff, HDIM, HDIM, HKP);
    k_convwT<<<dim3(ceildiv(DD*EVKP,256),1,LLAY*HH), 256>>>(W_key, wkvh, wkvl, DIN_, DD, EVKP);
    k_convwT<<<dim3(ceildiv(DD*EVKP,256),1,LLAY*HH), 256>>>(W_val, wkvh+kvoff, wkvl+kvoff, DIN_, DD, EVKP);

    // ---- builders ----
    k_build_ev<<<(int)(((long)MKV*EVKP + 255)/256), 256>>>(encoded, true_val);
    k_build_attin<<<(int)(((long)MQ*AIKP + 255)/256), 256>>>(encoded);

    // ---- K/V projections: wide N=2048 GEMM, keys/vals via z, slice-scatter epilogue ----
    {
        dim3 g(NKV/128, ceildiv(MKV, 128), 2);
        k_mma<0,0,2><<<g, 256, GSMEM>>>(evh, evl, wkvh, wkvl, b_key, keys, 0, 0,
                                        evh, evl, wkvh+kvoff, wkvl+kvoff, b_val, vals, 0, 0,
                                        MKV, NKV, EVKP);
    }

    // ---- shift ----
    {
        dim3 g(HDIM/128, ceildiv(MQ, 128), 1);
        k_mma<0,0,0><<<g, 256, GSMEM>>>(aih, ail, wshh, wshl, b_shift, attval, 0, 0,
                                        aih, ail, wshh, wshl, b_shift, attval, 0, 0,
                                        MQ, HDIM, AIKP);
    }

    // ---- transformer layers ----
    for (int l = 0; l < LLAY; l++) {
        k_attn2<<<BNN*HH, 128>>>(keys, vals, l);
        k_add_ln<<<MQ, 256>>>(attval, att, ln1_s + (long)l*HDIM, ln1_b + (long)l*HDIM);
        dim3 g(HDIM/128, ceildiv(MQ, 128), 1);
        k_mma<1,1,1><<<g, 256, GSMEM>>>(avh, avl, wf1h + (long)l*HDIM*HKP, wf1l + (long)l*HDIM*HKP,
                                        ff_b1 + (long)l*HDIM, 0, h1h, h1l,
                                        avh, avl, wf1h + (long)l*HDIM*HKP, wf1l + (long)l*HDIM*HKP,
                                        ff_b1 + (long)l*HDIM, 0, h1h, h1l,
                                        MQ, HDIM, HKP);
        k_mma<0,0,0><<<g, 256, GSMEM>>>(h1h, h1l, wf2h + (long)l*HDIM*HKP, wf2l + (long)l*HDIM*HKP,
                                        ff_b2 + (long)l*HDIM, att, 0, 0,
                                        h1h, h1l, wf2h + (long)l*HDIM*HKP, wf2l + (long)l*HDIM*HKP,
                                        ff_b2 + (long)l*HDIM, att, 0, 0,
                                        MQ, HDIM, HKP);
        k_add_ln<<<MQ, 256>>>(attval, att, ln2_s + (long)l*HDIM, ln2_b + (long)l*HDIM);
    }

    // ---- RealNVP flow ----
    k_build_inp_y<<<(int)(((long)MQ*INKP + 255)/256), 256>>>();
    k_init_u_mu<<<ceildiv(MQ, 256), 256>>>(true_val);

    dim3 gd(HDIM/128, ceildiv(MQ, 128), 2);

    for (int blk = 0; blk < NB_; blk++) {
        k_mma<2,1,1><<<gd, 256, GSMEM>>>(inh, inl, winh + (long)blk*HDIM*INKP, winl + (long)blk*HDIM*INKP,
                                         s_b_in + (long)blk*HDIM, 0, h1h, h1l,
                                         inh, inl, winh + inoff + (long)blk*HDIM*INKP, winl + inoff + (long)blk*HDIM*INKP,
                                         t_b_in + (long)blk*HDIM, 0, h3h, h3l,
                                         MQ, HDIM, INKP);
        unsigned *csh = h1h, *csl = h1l, *nsh = h2h, *nsl = h2l;
        unsigned *cth = h3h, *ctl = h3l, *nth = h4h, *ntl = h4l;
        for (int i = 0; i < NHID_; i++) {
            long wo = ((long)blk*NHID_ + i)*HDIM*HKP;
            k_mma<2,1,1><<<gd, 256, GSMEM>>>(csh, csl, whdh + wo, whdl + wo,
                                             s_b_hid + ((long)blk*NHID_ + i)*HDIM, 0, nsh, nsl,
                                             cth, ctl, whdh + hdoff + wo, whdl + hdoff + wo,
                                             t_b_hid + ((long)blk*NHID_ + i)*HDIM, 0, nth, ntl,
                                             MQ, HDIM, HKP);
            unsigned* t;
            t = csh; csh = nsh; nsh = t;  t = csl; csl = nsl; nsl = t;
            t = cth; cth = nth; nth = t;  t = ctl; ctl = ntl; ntl = t;
        }
        k_outrow<<<(2*MQ)/8, 256>>>(csh, csl, cth, ctl,
                                    s_w_out + (long)blk*HDIM*VV, s_b_out + (long)blk*VV,
                                    t_w_out + (long)blk*HDIM*VV, t_b_out + (long)blk*VV);
        k_coupling_stats<<<T2_*VV, 256>>>(blk);
        k_bn_apply_mu<<<ceildiv(MQ, 256), 256>>>(bn_lg + (long)blk*VV, bn_bt + (long)blk*VV, blk);
    }

    // ---- final NLL ----
    k_final<<<ceildiv(BNN, 256), 256>>>((float*)d_out);
}

// round 7
// speedup vs baseline: 3.7296x; 1.1121x over previous
#include <cuda_runtime.h>
#include <cuda_bf16.h>
#include <math.h>
#include <stdint.h>

// ---------------- problem dims ----------------
#define NV_   975
#define TT    48
#define T2_   12
#define CC    128
#define VV    3
#define HH    8
#define DD    64
#define HDIM  512
#define LLAY  4
#define NB_   6
#define NHID_ 4
#define DIN_  387
#define NVG   325
#define BNN   650
#define MKV   (BNN*TT)   // 31200
#define MQ    (BNN*T2_)  // 7800
#define LOG2PI_F 1.8378770664093453f

// k-pair counts (multiples of 16)
#define EVKP 208
#define AIKP 192
#define HKP  256
#define INKP 272

#define NKV  2048  // 32 (l,h) slices x 64

// ---------------- fp32 scratch ----------------
__device__ float g_keys[LLAY*HH*MKV*DD];
__device__ float g_vals[LLAY*HH*MKV*DD];
__device__ float g_attval[MQ*HDIM];
__device__ float g_att[MQ*HDIM];
__device__ float g_u[MQ*VV];
__device__ float g_ld[MQ*VV];
__device__ float g_bnstats[T2_*VV*2];

// ---------------- packed bf16 hi/lo activation planes (A: [M][KP2]) ----------------
__device__ __align__(128) unsigned a_ev_h[MKV*EVKP], a_ev_l[MKV*EVKP];
__device__ __align__(128) unsigned a_ai_h[MQ*AIKP],  a_ai_l[MQ*AIKP];
__device__ __align__(128) unsigned a_av_h[MQ*HKP],   a_av_l[MQ*HKP];
__device__ __align__(128) unsigned a_h1h[MQ*HKP], a_h1l[MQ*HKP];
__device__ __align__(128) unsigned a_h2h[MQ*HKP], a_h2l[MQ*HKP];
__device__ __align__(128) unsigned a_h3h[MQ*HKP], a_h3l[MQ*HKP];
__device__ __align__(128) unsigned a_h4h[MQ*HKP], a_h4l[MQ*HKP];
__device__ __align__(128) unsigned a_inh[MQ*INKP], a_inl[MQ*INKP];

// ---------------- transposed weight planes (B: [N][KP2], K-major rows) ----------------
__device__ __align__(128) unsigned w_shT_h[HDIM*AIKP], w_shT_l[HDIM*AIKP];
__device__ __align__(128) unsigned w_f1T_h[LLAY*HDIM*HKP], w_f1T_l[LLAY*HDIM*HKP];
__device__ __align__(128) unsigned w_f2T_h[LLAY*HDIM*HKP], w_f2T_l[LLAY*HDIM*HKP];
__device__ __align__(128) unsigned w_inT_h[2*NB_*HDIM*INKP], w_inT_l[2*NB_*HDIM*INKP];
__device__ __align__(128) unsigned w_hdT_h[2*NB_*NHID_*HDIM*HKP], w_hdT_l[2*NB_*NHID_*HDIM*HKP];
__device__ __align__(128) unsigned w_kvT_h[2*NKV*EVKP], w_kvT_l[2*NKV*EVKP];

// ---------------- helpers ----------------
__device__ __forceinline__ unsigned splitpack(float x0, float x1, unsigned& lo) {
    __nv_bfloat16 h0 = __float2bfloat16_rn(x0);
    __nv_bfloat16 h1 = __float2bfloat16_rn(x1);
    float r0 = x0 - __bfloat162float(h0);
    float r1 = x1 - __bfloat162float(h1);
    __nv_bfloat162 hp = __halves2bfloat162(h0, h1);
    __nv_bfloat162 lp = __halves2bfloat162(__float2bfloat16_rn(r0), __float2bfloat16_rn(r1));
    lo = *reinterpret_cast<unsigned*>(&lp);
    return *reinterpret_cast<unsigned*>(&hp);
}

__device__ __forceinline__ float2 unpack2(unsigned h, unsigned l) {
    __nv_bfloat162 hb = *reinterpret_cast<__nv_bfloat162*>(&h);
    __nv_bfloat162 lb = *reinterpret_cast<__nv_bfloat162*>(&l);
    float2 r;
    r.x = __bfloat162float(hb.x) + __bfloat162float(lb.x);
    r.y = __bfloat162float(hb.y) + __bfloat162float(lb.y);
    return r;
}

__device__ __forceinline__ void cpa16s(unsigned saddr, const void* gsrc) {
    asm volatile("cp.async.cg.shared.global [%0], [%1], 16;" :: "r"(saddr), "l"(gsrc));
}

__device__ __forceinline__ void mma16(float* c, const unsigned* a, const unsigned* b) {
    asm volatile(
        "mma.sync.aligned.m16n8k16.row.col.f32.bf16.bf16.f32 "
        "{%0,%1,%2,%3}, {%4,%5,%6,%7}, {%8,%9}, {%0,%1,%2,%3};"
        : "+f"(c[0]), "+f"(c[1]), "+f"(c[2]), "+f"(c[3])
        : "r"(a[0]), "r"(a[1]), "r"(a[2]), "r"(a[3]), "r"(b[0]), "r"(b[1]));
}

template <int A> __device__ __forceinline__ float actf(float v) {
    if (A == 1) return fmaxf(v, 0.f);
    if (A == 2) return tanhf(v);
    return v;
}

// ---------------- weight pre-conversion (transposed: [Z][K][N] -> [Z][N][KP2]) ----------------
__global__ void k_convwT(const float* __restrict__ src, unsigned* __restrict__ dhi,
                         unsigned* __restrict__ dlo, int K, int N, int KP2) {
    long z = blockIdx.z;
    src += z * (long)K * N;
    dhi += z * (long)N * KP2;
    dlo += z * (long)N * KP2;
    int idx = blockIdx.x * 256 + threadIdx.x;
    if (idx >= N * KP2) return;
    int n = idx / KP2, kp = idx - n * KP2;
    float x0 = (2 * kp     < K) ? src[(long)(2 * kp) * N + n]     : 0.f;
    float x1 = (2 * kp + 1 < K) ? src[(long)(2 * kp + 1) * N + n] : 0.f;
    unsigned lo, hi = splitpack(x0, x1, lo);
    dhi[idx] = hi; dlo[idx] = lo;
}

// ---------------- builders ----------------
__global__ void k_build_ev(const float* __restrict__ enc, const float* __restrict__ tv) {
    long idx = (long)blockIdx.x * 256 + threadIdx.x;
    if (idx >= (long)MKV * EVKP) return;
    int kp = (int)(idx % EVKP);
    int m  = (int)(idx / EVKP);
    int b = m / TT, tt = m % TT;
    int ob = b / NVG, nvb = (b % NVG) * VV;
    float x[2];
#pragma unroll
    for (int t = 0; t < 2; t++) {
        int e = 2 * kp + t;
        float v = 0.f;
        if (e < DIN_) {
            int vv = e / (CC + 1), cc = e % (CC + 1);
            int nv = nvb + vv;
            if (cc < CC) v = enc[(((long)ob * NV_ + nv) * TT + tt) * CC + cc];
            else         v = tv[((long)ob * NV_ + nv) * TT + tt];
        }
        x[t] = v;
    }
    unsigned lo, hi = splitpack(x[0], x[1], lo);
    a_ev_h[idx] = hi; a_ev_l[idx] = lo;
}

__global__ void k_build_attin(const float* __restrict__ enc) {
    long idx = (long)blockIdx.x * 256 + threadIdx.x;
    if (idx >= (long)MQ * AIKP) return;
    int kp = (int)(idx % AIKP);
    int m  = (int)(idx / AIKP);
    int b = m / T2_, q = m % T2_;
    int ob = b / NVG, nvb = (b % NVG) * VV;
    float x[2];
#pragma unroll
    for (int t = 0; t < 2; t++) {
        int e = 2 * kp + t;
        int vv = e / CC, cc = e % CC;
        x[t] = enc[(((long)ob * NV_ + nvb + vv) * TT + (TT - T2_) + q) * CC + cc];
    }
    unsigned lo, hi = splitpack(x[0], x[1], lo);
    a_ai_h[idx] = hi; a_ai_l[idx] = lo;
}

__global__ void k_build_inp_y() {
    long idx = (long)blockIdx.x * 256 + threadIdx.x;
    if (idx >= (long)MQ * INKP) return;
    int kp = (int)(idx % INKP);
    int m  = (int)(idx / INKP);
    if (kp < HKP) {
        a_inh[idx] = a_av_h[(long)m * HKP + kp];
        a_inl[idx] = a_av_l[(long)m * HKP + kp];
    } else if (kp >= 258) {
        a_inh[idx] = 0u; a_inl[idx] = 0u;
    }
}

__global__ void k_init_u_mu(const float* __restrict__ tv) {
    int m = blockIdx.x * 256 + threadIdx.x;
    if (m >= MQ) return;
    int b = m / T2_, q = m % T2_;
    int ob = b / NVG, nvb = (b % NVG) * VV;
    float u[3];
#pragma unroll
    for (int v = 0; v < 3; v++) {
        u[v] = tv[((long)ob * NV_ + nvb + v) * TT + (TT - T2_) + q];
        g_u[m * 3 + v] = u[v];
        g_ld[m * 3 + v] = 0.f;
    }
    unsigned lo, hi;
    hi = splitpack(0.f, u[1], lo);
    a_inh[(long)m * INKP + 256] = hi; a_inl[(long)m * INKP + 256] = lo;
    hi = splitpack(0.f, 0.f, lo);
    a_inh[(long)m * INKP + 257] = hi; a_inl[(long)m * INKP + 257] = lo;
}

// pure batch-norm statistics over rows (coupling now fused into out-layer)
__global__ void k_stats() {
    int col = blockIdx.x;
    int tid = threadIdx.x;
    __shared__ float rs[256], rq[256];
    float s = 0.f, q = 0.f;
    for (int b = tid; b < BNN; b += 256) {
        float u = g_u[b * (T2_ * VV) + col];
        s += u; q += u * u;
    }
    rs[tid] = s; rq[tid] = q;
    __syncthreads();
    for (int st = 128; st > 0; st >>= 1) {
        if (tid < st) { rs[tid] += rs[tid + st]; rq[tid] += rq[tid + st]; }
        __syncthreads();
    }
    if (tid == 0) {
        float mean = rs[0] / (float)BNN;
        float var  = rq[0] / (float)BNN - mean * mean;
        g_bnstats[col * 2 + 0] = mean;
        g_bnstats[col * 2 + 1] = var;
    }
}

__global__ void k_bn_apply_mu(const float* __restrict__ lgam, const float* __restrict__ beta, int blk) {
    int m = blockIdx.x * 256 + threadIdx.x;
    if (m >= MQ) return;
    int t2 = m % T2_;
    float mu[3];
#pragma unroll
    for (int v = 0; v < 3; v++) {
        int col = t2 * 3 + v;
        float mean = g_bnstats[col * 2 + 0];
        float var  = g_bnstats[col * 2 + 1];
        float lg = lgam[v], bt = beta[v];
        float u = expf(lg) * (g_u[m * 3 + v] - mean) * rsqrtf(var + 1e-5f) + bt;
        g_u[m * 3 + v] = u;
        g_ld[m * 3 + v] += lg - 0.5f * logf(var + 1e-5f);
        int nmask = (v + blk + 1) & 1;
        mu[v] = nmask ? u : 0.f;
    }
    if (blk < NB_ - 1) {
        unsigned lo, hi;
        hi = splitpack(mu[0], mu[1], lo);
        a_inh[(long)m * INKP + 256] = hi; a_inl[(long)m * INKP + 256] = lo;
        hi = splitpack(mu[2], 0.f, lo);
        a_inh[(long)m * INKP + 257] = hi; a_inl[(long)m * INKP + 257] = lo;
    }
}

__global__ void k_final(float* __restrict__ out) {
    int b = blockIdx.x * 256 + threadIdx.x;
    if (b >= BNN) return;
    float acc = 0.f;
    for (int i = 0; i < T2_ * VV; i++) {
        float u = g_u[b * (T2_ * VV) + i];
        acc += 0.5f * u * u + 0.5f * LOG2PI_F - g_ld[b * (T2_ * VV) + i];
    }
    out[b] = acc;
}

// ---------------- bf16x3 HMMA GEMM, 128x128 block tile ----------------
#define PITCH 20
#define PLW   (128*PITCH)
#define STW   (4*PLW)
#define GSMEM (2*STW*4)

// CM: 0 = fp32 C row-major; 1 = packed planes Ph/Pl; 2 = KV scatter C[slice][m][64]
template <int ACT0, int ACT1, int CM>
__global__ void __launch_bounds__(256, 2)
k_mma(const unsigned* __restrict__ Ah0, const unsigned* __restrict__ Al0,
      const unsigned* __restrict__ Wh0, const unsigned* __restrict__ Wl0,
      const float* __restrict__ b0, float* __restrict__ C0,
      unsigned* __restrict__ Ph0, unsigned* __restrict__ Pl0,
      const unsigned* __restrict__ Ah1, const unsigned* __restrict__ Al1,
      const unsigned* __restrict__ Wh1, const unsigned* __restrict__ Wl1,
      const float* __restrict__ b1, float* __restrict__ C1,
      unsigned* __restrict__ Ph1, unsigned* __restrict__ Pl1,
      int M, int N, int KP2) {
    extern __shared__ __align__(16) unsigned dsm[];

    bool first = (blockIdx.z == 0);
    const unsigned* Ah = first ? Ah0 : Ah1;
    const unsigned* Al = first ? Al0 : Al1;
    const unsigned* Wh = first ? Wh0 : Wh1;
    const unsigned* Wl = first ? Wl0 : Wl1;
    const float* bias  = first ? b0 : b1;
    float* C           = first ? C0 : C1;
    unsigned* Ph       = first ? Ph0 : Ph1;
    unsigned* Pl       = first ? Pl0 : Pl1;

    int tile_m = blockIdx.y * 128;
    int tile_n = blockIdx.x * 128;
    int tid = threadIdx.x, lane = tid & 31, wid = tid >> 5;
    int grp = lane >> 2, tig = lane & 3;
    int wm = wid & 3, wn = wid >> 2;
    unsigned sbb = (unsigned)__cvta_generic_to_shared(dsm);

    float acc[2][8][4];
#pragma unroll
    for (int i = 0; i < 2; i++)
#pragma unroll
        for (int j = 0; j < 8; j++)
#pragma unroll
            for (int e = 0; e < 4; e++) acc[i][j][e] = 0.f;

    auto load_stage = [&](int st, int kp0) {
        unsigned base = (unsigned)st * STW;
#pragma unroll
        for (int t = 0; t < 4; t++) {
            int idx = tid + t * 256;
            int p = idx >> 9, r = (idx >> 2) & 127, c = idx & 3;
            int gm = tile_m + r; if (gm >= M) gm = M - 1;
            const unsigned* src = (p ? Al : Ah) + (long)gm * KP2 + kp0 + c * 4;
            cpa16s(sbb + (base + (unsigned)p * PLW + (unsigned)(r * PITCH + c * 4)) * 4u, src);
        }
#pragma unroll
        for (int t = 0; t < 4; t++) {
            int idx = tid + t * 256;
            int p = idx >> 9, r = (idx >> 2) & 127, c = idx & 3;
            int gn = tile_n + r;
            const unsigned* src = (p ? Wl : Wh) + (long)gn * KP2 + kp0 + c * 4;
            cpa16s(sbb + (base + 2u * PLW + (unsigned)p * PLW + (unsigned)(r * PITCH + c * 4)) * 4u, src);
        }
        asm volatile("cp.async.commit_group;" ::: "memory");
    };

    int iters = KP2 / 16;
    load_stage(0, 0);

    for (int it = 0; it < iters; it++) {
        if (it + 1 < iters) {
            load_stage((it + 1) & 1, (it + 1) * 16);
            asm volatile("cp.async.wait_group 1;" ::: "memory");
        } else {
            asm volatile("cp.async.wait_group 0;" ::: "memory");
        }
        __syncthreads();

        unsigned base = (unsigned)(it & 1) * STW;
        const unsigned* SAh = dsm + base;
        const unsigned* SAl = dsm + base + PLW;
        const unsigned* SBh = dsm + base + 2 * PLW;
        const unsigned* SBl = dsm + base + 3 * PLW;

#pragma unroll
        for (int s2 = 0; s2 < 2; s2++) {
            int kb = s2 * 8;
            unsigned ah[2][4], al[2][4];
#pragma unroll
            for (int i = 0; i < 2; i++) {
                int rb = wm * 32 + i * 16 + grp;
                ah[i][0] = SAh[rb * PITCH + kb + tig];
                ah[i][1] = SAh[(rb + 8) * PITCH + kb + tig];
                ah[i][2] = SAh[rb * PITCH + kb + tig + 4];
                ah[i][3] = SAh[(rb + 8) * PITCH + kb + tig + 4];
                al[i][0] = SAl[rb * PITCH + kb + tig];
                al[i][1] = SAl[(rb + 8) * PITCH + kb + tig];
                al[i][2] = SAl[rb * PITCH + kb + tig + 4];
                al[i][3] = SAl[(rb + 8) * PITCH + kb + tig + 4];
            }
#pragma unroll
            for (int j = 0; j < 8; j++) {
                int nb = wn * 64 + j * 8 + grp;
                unsigned bh[2], bl[2];
                bh[0] = SBh[nb * PITCH + kb + tig];
                bh[1] = SBh[nb * PITCH + kb + tig + 4];
                bl[0] = SBl[nb * PITCH + kb + tig];
                bl[1] = SBl[nb * PITCH + kb + tig + 4];
#pragma unroll
                for (int i = 0; i < 2; i++) {
                    mma16(acc[i][j], ah[i], bh);
                    mma16(acc[i][j], al[i], bh);
                    mma16(acc[i][j], ah[i], bl);
                }
            }
        }
        __syncthreads();
    }

    int np2 = N >> 1;
#pragma unroll
    for (int i = 0; i < 2; i++) {
        int row0 = tile_m + wm * 32 + i * 16 + grp;
        int row1 = row0 + 8;
#pragma unroll
        for (int j = 0; j < 8; j++) {
            int col = tile_n + wn * 64 + j * 8 + tig * 2;
            float b0v = bias[col], b1v = bias[col + 1];
            float v00 = acc[i][j][0] + b0v, v01 = acc[i][j][1] + b1v;
            float v10 = acc[i][j][2] + b0v, v11 = acc[i][j][3] + b1v;
            if (first) {
                v00 = actf<ACT0>(v00); v01 = actf<ACT0>(v01);
                v10 = actf<ACT0>(v10); v11 = actf<ACT0>(v11);
            } else {
                v00 = actf<ACT1>(v00); v01 = actf<ACT1>(v01);
                v10 = actf<ACT1>(v10); v11 = actf<ACT1>(v11);
            }
            if (CM == 2) {
                int slice = col >> 6, cis = col & 63;
                float* d0 = C + ((long)slice * M + row0) * 64 + cis;
                float* d1 = C + ((long)slice * M + row1) * 64 + cis;
                if (row0 < M) { d0[0] = v00; d0[1] = v01; }
                if (row1 < M) { d1[0] = v10; d1[1] = v11; }
            } else if (CM == 0) {
                if (row0 < M) { C[(long)row0 * N + col] = v00; C[(long)row0 * N + col + 1] = v01; }
                if (row1 < M) { C[(long)row1 * N + col] = v10; C[(long)row1 * N + col + 1] = v11; }
            } else {
                unsigned lo, hi;
                if (row0 < M) {
                    hi = splitpack(v00, v01, lo);
                    Ph[(long)row0 * np2 + (col >> 1)] = hi;
                    Pl[(long)row0 * np2 + (col >> 1)] = lo;
                }
                if (row1 < M) {
                    hi = splitpack(v10, v11, lo);
                    Ph[(long)row1 * np2 + (col >> 1)] = hi;
                    Pl[(long)row1 * np2 + (col >> 1)] = lo;
                }
            }
        }
    }
}

// ---------------- flow out-layer + coupling fused: warp per row, both nets ----------------
__global__ void k_outcpl(const unsigned* __restrict__ hsh, const unsigned* __restrict__ hsl,
                         const unsigned* __restrict__ hth, const unsigned* __restrict__ htl,
                         const float* __restrict__ sw, const float* __restrict__ sb,
                         const float* __restrict__ tw, const float* __restrict__ tb, int blk) {
    __shared__ float Ws[2][HDIM * VV];
    __shared__ float Wb[2][VV];
    int tid = threadIdx.x;
    for (int i = tid; i < HDIM * VV; i += 256) { Ws[0][i] = sw[i]; Ws[1][i] = tw[i]; }
    if (tid < VV) { Wb[0][tid] = sb[tid]; Wb[1][tid] = tb[tid]; }
    __syncthreads();

    int r = blockIdx.x * 8 + (tid >> 5);   // row 0..MQ-1
    int lane = tid & 31;
    float s0 = 0.f, s1 = 0.f, s2 = 0.f, t0 = 0.f, t1 = 0.f, t2 = 0.f;
    for (int cp = lane; cp < HKP; cp += 32) {
        float2 vs = unpack2(hsh[(long)r * HKP + cp], hsl[(long)r * HKP + cp]);
        float2 vt = unpack2(hth[(long)r * HKP + cp], htl[(long)r * HKP + cp]);
        int c0 = 2 * cp;
        const float* W0 = Ws[0]; const float* W1 = Ws[1];
        s0 += vs.x * W0[c0 * 3 + 0] + vs.y * W0[(c0 + 1) * 3 + 0];
        s1 += vs.x * W0[c0 * 3 + 1] + vs.y * W0[(c0 + 1) * 3 + 1];
        s2 += vs.x * W0[c0 * 3 + 2] + vs.y * W0[(c0 + 1) * 3 + 2];
        t0 += vt.x * W1[c0 * 3 + 0] + vt.y * W1[(c0 + 1) * 3 + 0];
        t1 += vt.x * W1[c0 * 3 + 1] + vt.y * W1[(c0 + 1) * 3 + 1];
        t2 += vt.x * W1[c0 * 3 + 2] + vt.y * W1[(c0 + 1) * 3 + 2];
    }
#pragma unroll
    for (int o = 16; o; o >>= 1) {
        s0 += __shfl_xor_sync(0xffffffffu, s0, o);
        s1 += __shfl_xor_sync(0xffffffffu, s1, o);
        s2 += __shfl_xor_sync(0xffffffffu, s2, o);
        t0 += __shfl_xor_sync(0xffffffffu, t0, o);
        t1 += __shfl_xor_sync(0xffffffffu, t1, o);
        t2 += __shfl_xor_sync(0xffffffffu, t2, o);
    }
    if (lane == 0) {
        float sv[3] = { s0 + Wb[0][0], s1 + Wb[0][1], s2 + Wb[0][2] };
        float tv_[3] = { t0 + Wb[1][0], t1 + Wb[1][1], t2 + Wb[1][2] };
#pragma unroll
        for (int v = 0; v < 3; v++) {
            int mask = (v + blk) & 1;
            if (!mask) {
                float u = (g_u[r * 3 + v] - tv_[v]) * expf(-sv[v]);
                g_u[r * 3 + v] = u;
                g_ld[r * 3 + v] -= sv[v];
            }
        }
    }
}

// ---------------- attention ----------------
__global__ void k_attn2(const float* __restrict__ keys, const float* __restrict__ vals, int l) {
    int h = blockIdx.x & 7, b = blockIdx.x >> 3;
    int tid = threadIdx.x, lane = tid & 31, wq = tid >> 5;
    __shared__ float KsT[DD * TT];
    __shared__ float Vs[TT * DD];
    __shared__ float Qs[T2_ * DD];
    __shared__ float Ps[4][64];

    long base = ((long)(l * HH + h) * MKV + (long)b * TT) * DD;
    const float4* k4 = (const float4*)(keys + base);
    const float4* v4 = (const float4*)(vals + base);
    for (int i = tid; i < TT * DD / 4; i += 128) {
        float4 kv = k4[i];
        int w = i >> 4, d = (i & 15) << 2;
        KsT[(d + 0) * TT + w] = kv.x;
        KsT[(d + 1) * TT + w] = kv.y;
        KsT[(d + 2) * TT + w] = kv.z;
        KsT[(d + 3) * TT + w] = kv.w;
        ((float4*)Vs)[i] = v4[i];
    }
    for (int i = tid; i < T2_ * DD / 4; i += 128) {
        int q = i >> 4, d4 = (i & 15);
        ((float4*)Qs)[i] = *(const float4*)(g_attval + (long)(b * T2_ + q) * HDIM + h * DD + d4 * 4);
    }
    __syncthreads();

#pragma unroll
    for (int qi = 0; qi < 3; qi++) {
        int q = wq + qi * 4;
        int lim = (TT - T2_) + q;
        float d0 = 0.f, d1 = 0.f;
        const float* qrow = Qs + q * DD;
#pragma unroll
        for (int d = 0; d < DD; d++) {
            float qd = qrow[d];
            d0 += qd * KsT[d * TT + lane];
            d1 += qd * KsT[d * TT + ((lane + 32) & 63)];
        }
        float s0 = (lane < lim) ? d0 * 0.125f : -1e30f;
        float s1 = (lane + 32 < lim) ? d1 * 0.125f : -1e30f;
        float mx = fmaxf(s0, s1);
#pragma unroll
        for (int o = 16; o; o >>= 1) mx = fmaxf(mx, __shfl_xor_sync(0xffffffffu, mx, o));
        float e0 = (lane < lim) ? expf(s0 - mx) : 0.f;
        float e1 = (lane + 32 < lim) ? expf(s1 - mx) : 0.f;
        float sm = e0 + e1;
#pragma unroll
        for (int o = 16; o; o >>= 1) sm += __shfl_xor_sync(0xffffffffu, sm, o);
        Ps[wq][lane] = e0;
        Ps[wq][lane + 32] = e1;
        __syncwarp();
        float inv = 1.f / sm;
        float o0 = 0.f, o1 = 0.f;
        for (int w2 = 0; w2 < lim; w2++) {
            float p = Ps[wq][w2];
            o0 += p * Vs[w2 * DD + lane];
            o1 += p * Vs[w2 * DD + lane + 32];
        }
        long orow = (long)(b * T2_ + q) * HDIM + h * DD;
        g_att[orow + lane] = o0 * inv;
        g_att[orow + lane + 32] = o1 * inv;
        __syncwarp();
    }
}

// ---------------- add + layernorm; emits fp32 + packed planes ----------------
__global__ void k_add_ln(float* __restrict__ x, const float* __restrict__ y,
                         const float* __restrict__ gamma, const float* __restrict__ beta) {
    int m = blockIdx.x;
    int tid = threadIdx.x;
    long base = (long)m * HDIM;
    float2 xx = *(const float2*)&x[base + 2 * tid];
    float2 yy = *(const float2*)&y[base + 2 * tid];
    float v0 = xx.x + yy.x, v1 = xx.y + yy.y;
    __shared__ float red[256];
    __shared__ float s_mean, s_rstd;
    red[tid] = v0 + v1;
    __syncthreads();
    for (int st = 128; st > 0; st >>= 1) {
        if (tid < st) red[tid] += red[tid + st];
        __syncthreads();
    }
    if (tid == 0) s_mean = red[0] / (float)HDIM;
    __syncthreads();
    float mn = s_mean;
    float d0 = v0 - mn, d1 = v1 - mn;
    red[tid] = d0 * d0 + d1 * d1;
    __syncthreads();
    for (int st = 128; st > 0; st >>= 1) {
        if (tid < st) red[tid] += red[tid + st];
        __syncthreads();
    }
    if (tid == 0) s_rstd = rsqrtf(red[0] / (float)HDIM + 1e-5f);
    __syncthreads();
    float r = s_rstd;
    float o0 = d0 * r * gamma[2 * tid]     + beta[2 * tid];
    float o1 = d1 * r * gamma[2 * tid + 1] + beta[2 * tid + 1];
    float2 oo; oo.x = o0; oo.y = o1;
    *(float2*)&x[base + 2 * tid] = oo;
    unsigned lo, hi = splitpack(o0, o1, lo);
    a_av_h[(long)m * HKP + tid] = hi;
    a_av_l[(long)m * HKP + tid] = lo;
}

// ---------------- host ----------------
static inline int ceildiv(int a, int b) { return (a + b - 1) / b; }

extern "C" void kernel_launch(void* const* d_in, const int* in_sizes, int n_in,
                              void* d_out, int out_size) {
    const float* encoded   = (const float*)d_in[0];
    const float* true_val  = (const float*)d_in[1];
    const float* W_shift   = (const float*)d_in[2];
    const float* b_shift   = (const float*)d_in[3];
    const float* W_key     = (const float*)d_in[4];
    const float* b_key     = (const float*)d_in[5];
    const float* W_val     = (const float*)d_in[6];
    const float* b_val     = (const float*)d_in[7];
    const float* ln1_s     = (const float*)d_in[8];
    const float* ln1_b     = (const float*)d_in[9];
    const float* ff_w1     = (const float*)d_in[10];
    const float* ff_b1     = (const float*)d_in[11];
    const float* ff_w2     = (const float*)d_in[12];
    const float* ff_b2     = (const float*)d_in[13];
    const float* ln2_s     = (const float*)d_in[14];
    const float* ln2_b     = (const float*)d_in[15];
    const float* s_w_in    = (const float*)d_in[16];
    const float* s_b_in    = (const float*)d_in[17];
    const float* s_w_hid   = (const float*)d_in[18];
    const float* s_b_hid   = (const float*)d_in[19];
    const float* s_w_out   = (const float*)d_in[20];
    const float* s_b_out   = (const float*)d_in[21];
    const float* t_w_in    = (const float*)d_in[22];
    const float* t_b_in    = (const float*)d_in[23];
    const float* t_w_hid   = (const float*)d_in[24];
    const float* t_b_hid   = (const float*)d_in[25];
    const float* t_w_out   = (const float*)d_in[26];
    const float* t_b_out   = (const float*)d_in[27];
    const float* bn_lg     = (const float*)d_in[28];
    const float* bn_bt     = (const float*)d_in[29];

    float *keys, *vals, *attval, *att;
    unsigned *evh, *evl, *aih, *ail, *avh, *avl;
    unsigned *h1h, *h1l, *h2h, *h2l, *h3h, *h3l, *h4h, *h4l, *inh, *inl;
    unsigned *wshh, *wshl, *wf1h, *wf1l, *wf2h, *wf2l, *winh, *winl, *whdh, *whdl, *wkvh, *wkvl;
    cudaGetSymbolAddress((void**)&keys,   g_keys);
    cudaGetSymbolAddress((void**)&vals,   g_vals);
    cudaGetSymbolAddress((void**)&attval, g_attval);
    cudaGetSymbolAddress((void**)&att,    g_att);
    cudaGetSymbolAddress((void**)&evh, a_ev_h);  cudaGetSymbolAddress((void**)&evl, a_ev_l);
    cudaGetSymbolAddress((void**)&aih, a_ai_h);  cudaGetSymbolAddress((void**)&ail, a_ai_l);
    cudaGetSymbolAddress((void**)&avh, a_av_h);  cudaGetSymbolAddress((void**)&avl, a_av_l);
    cudaGetSymbolAddress((void**)&h1h, a_h1h);   cudaGetSymbolAddress((void**)&h1l, a_h1l);
    cudaGetSymbolAddress((void**)&h2h, a_h2h);   cudaGetSymbolAddress((void**)&h2l, a_h2l);
    cudaGetSymbolAddress((void**)&h3h, a_h3h);   cudaGetSymbolAddress((void**)&h3l, a_h3l);
    cudaGetSymbolAddress((void**)&h4h, a_h4h);   cudaGetSymbolAddress((void**)&h4l, a_h4l);
    cudaGetSymbolAddress((void**)&inh, a_inh);   cudaGetSymbolAddress((void**)&inl, a_inl);
    cudaGetSymbolAddress((void**)&wshh, w_shT_h); cudaGetSymbolAddress((void**)&wshl, w_shT_l);
    cudaGetSymbolAddress((void**)&wf1h, w_f1T_h); cudaGetSymbolAddress((void**)&wf1l, w_f1T_l);
    cudaGetSymbolAddress((void**)&wf2h, w_f2T_h); cudaGetSymbolAddress((void**)&wf2l, w_f2T_l);
    cudaGetSymbolAddress((void**)&winh, w_inT_h); cudaGetSymbolAddress((void**)&winl, w_inT_l);
    cudaGetSymbolAddress((void**)&whdh, w_hdT_h); cudaGetSymbolAddress((void**)&whdl, w_hdT_l);
    cudaGetSymbolAddress((void**)&wkvh, w_kvT_h); cudaGetSymbolAddress((void**)&wkvl, w_kvT_l);

    cudaFuncSetAttribute(k_mma<0,0,0>, cudaFuncAttributeMaxDynamicSharedMemorySize, GSMEM);
    cudaFuncSetAttribute(k_mma<0,0,2>, cudaFuncAttributeMaxDynamicSharedMemorySize, GSMEM);
    cudaFuncSetAttribute(k_mma<1,1,1>, cudaFuncAttributeMaxDynamicSharedMemorySize, GSMEM);
    cudaFuncSetAttribute(k_mma<2,2,1>, cudaFuncAttributeMaxDynamicSharedMemorySize, GSMEM);

    // side stream + events for fork-join (created per call; graph capture encodes deps)
    cudaStream_t s2;
    cudaStreamCreateWithFlags(&s2, cudaStreamNonBlocking);
    cudaEvent_t evF, evT;
    cudaEventCreateWithFlags(&evF, cudaEventDisableTiming);
    cudaEventCreateWithFlags(&evT, cudaEventDisableTiming);

    long kvoff = (long)NKV * EVKP;
    long inoff = (long)NB_ * HDIM * INKP;
    long hdoff = (long)NB_ * NHID_ * HDIM * HKP;

    // ---- launches 0-4: KV weight conversion + builders (so launch #5 = KV GEMM for ncu) ----
    k_convwT<<<dim3(ceildiv(DD*EVKP,256),1,LLAY*HH), 256>>>(W_key, wkvh, wkvl, DIN_, DD, EVKP);          // 0
    k_convwT<<<dim3(ceildiv(DD*EVKP,256),1,LLAY*HH), 256>>>(W_val, wkvh+kvoff, wkvl+kvoff, DIN_, DD, EVKP); // 1
    k_build_ev<<<(int)(((long)MKV*EVKP + 255)/256), 256>>>(encoded, true_val);                           // 2
    k_build_attin<<<(int)(((long)MQ*AIKP + 255)/256), 256>>>(encoded);                                   // 3
    k_init_u_mu<<<ceildiv(MQ, 256), 256>>>(true_val);                                                    // 4

    // ---- launch 5: KV projections (wide N=2048, keys/vals via z, slice scatter) ----
    {
        dim3 g(NKV/128, ceildiv(MKV, 128), 2);
        k_mma<0,0,2><<<g, 256, GSMEM>>>(evh, evl, wkvh, wkvl, b_key, keys, 0, 0,
                                        evh, evl, wkvh+kvoff, wkvl+kvoff, b_val, vals, 0, 0,
                                        MKV, NKV, EVKP);
    }

    // ---- remaining weight conversions ----
    k_convwT<<<dim3(ceildiv(HDIM*AIKP,256),1,1), 256>>>(W_shift, wshh, wshl, VV*CC, HDIM, AIKP);
    k_convwT<<<dim3(ceildiv(HDIM*HKP,256),1,LLAY), 256>>>(ff_w1, wf1h, wf1l, HDIM, HDIM, HKP);
    k_convwT<<<dim3(ceildiv(HDIM*HKP,256),1,LLAY), 256>>>(ff_w2, wf2h, wf2l, HDIM, HDIM, HKP);
    k_convwT<<<dim3(ceildiv(HDIM*INKP,256),1,NB_), 256>>>(s_w_in, winh, winl, HDIM+VV, HDIM, INKP);
    k_convwT<<<dim3(ceildiv(HDIM*INKP,256),1,NB_), 256>>>(t_w_in, winh+inoff, winl+inoff, HDIM+VV, HDIM, INKP);
    k_convwT<<<dim3(ceildiv(HDIM*HKP,256),1,NB_*NHID_), 256>>>(s_w_hid, whdh, whdl, HDIM, HDIM, HKP);
    k_convwT<<<dim3(ceildiv(HDIM*HKP,256),1,NB_*NHID_), 256>>>(t_w_hid, whdh+hdoff, whdl+hdoff, HDIM, HDIM, HKP);

    // ---- shift ----
    {
        dim3 g(HDIM/128, ceildiv(MQ, 128), 1);
        k_mma<0,0,0><<<g, 256, GSMEM>>>(aih, ail, wshh, wshl, b_shift, attval, 0, 0,
                                        aih, ail, wshh, wshl, b_shift, attval, 0, 0,
                                        MQ, HDIM, AIKP);
    }

    // ---- transformer layers ----
    for (int l = 0; l < LLAY; l++) {
        k_attn2<<<BNN*HH, 128>>>(keys, vals, l);
        k_add_ln<<<MQ, 256>>>(attval, att, ln1_s + (long)l*HDIM, ln1_b + (long)l*HDIM);
        dim3 g(HDIM/128, ceildiv(MQ, 128), 1);
        k_mma<1,1,1><<<g, 256, GSMEM>>>(avh, avl, wf1h + (long)l*HDIM*HKP, wf1l + (long)l*HDIM*HKP,
                                        ff_b1 + (long)l*HDIM, 0, h1h, h1l,
                                        avh, avl, wf1h + (long)l*HDIM*HKP, wf1l + (long)l*HDIM*HKP,
                                        ff_b1 + (long)l*HDIM, 0, h1h, h1l,
                                        MQ, HDIM, HKP);
        k_mma<0,0,0><<<g, 256, GSMEM>>>(h1h, h1l, wf2h + (long)l*HDIM*HKP, wf2l + (long)l*HDIM*HKP,
                                        ff_b2 + (long)l*HDIM, att, 0, 0,
                                        h1h, h1l, wf2h + (long)l*HDIM*HKP, wf2l + (long)l*HDIM*HKP,
                                        ff_b2 + (long)l*HDIM, att, 0, 0,
                                        MQ, HDIM, HKP);
        k_add_ln<<<MQ, 256>>>(attval, att, ln2_s + (long)l*HDIM, ln2_b + (long)l*HDIM);
    }

    // ---- RealNVP flow: s-chain on default stream, t-chain forked onto s2 ----
    k_build_inp_y<<<(int)(((long)MQ*INKP + 255)/256), 256>>>();

    dim3 gs(HDIM/128, ceildiv(MQ, 128), 1);

    for (int blk = 0; blk < NB_; blk++) {
        // fork: inp is ready on main stream
        cudaEventRecord(evF, 0);
        cudaStreamWaitEvent(s2, evF, 0);

        // s-chain (tanh) on main
        k_mma<2,2,1><<<gs, 256, GSMEM>>>(inh, inl, winh + (long)blk*HDIM*INKP, winl + (long)blk*HDIM*INKP,
                                         s_b_in + (long)blk*HDIM, 0, h1h, h1l,
                                         inh, inl, winh + (long)blk*HDIM*INKP, winl + (long)blk*HDIM*INKP,
                                         s_b_in + (long)blk*HDIM, 0, h1h, h1l,
                                         MQ, HDIM, INKP);
        // t-chain (relu) on s2
        k_mma<1,1,1><<<gs, 256, GSMEM, s2>>>(inh, inl, winh + inoff + (long)blk*HDIM*INKP, winl + inoff + (long)blk*HDIM*INKP,
                                             t_b_in + (long)blk*HDIM, 0, h3h, h3l,
                                             inh, inl, winh + inoff + (long)blk*HDIM*INKP, winl + inoff + (long)blk*HDIM*INKP,
                                             t_b_in + (long)blk*HDIM, 0, h3h, h3l,
                                             MQ, HDIM, INKP);

        unsigned *csh = h1h, *csl = h1l, *nsh = h2h, *nsl = h2l;
        unsigned *cth = h3h, *ctl = h3l, *nth = h4h, *ntl = h4l;
        for (int i = 0; i < NHID_; i++) {
            long wo = ((long)blk*NHID_ + i)*HDIM*HKP;
            k_mma<2,2,1><<<gs, 256, GSMEM>>>(csh, csl, whdh + wo, whdl + wo,
                                             s_b_hid + ((long)blk*NHID_ + i)*HDIM, 0, nsh, nsl,
                                             csh, csl, whdh + wo, whdl + wo,
                                             s_b_hid + ((long)blk*NHID_ + i)*HDIM, 0, nsh, nsl,
                                             MQ, HDIM, HKP);
            k_mma<1,1,1><<<gs, 256, GSMEM, s2>>>(cth, ctl, whdh + hdoff + wo, whdl + hdoff + wo,
                                                 t_b_hid + ((long)blk*NHID_ + i)*HDIM, 0, nth, ntl,
                                                 cth, ctl, whdh + hdoff + wo, whdl + hdoff + wo,
                                                 t_b_hid + ((long)blk*NHID_ + i)*HDIM, 0, nth, ntl,
                                                 MQ, HDIM, HKP);
            unsigned* t;
            t = csh; csh = nsh; nsh = t;  t = csl; csl = nsl; nsl = t;
            t = cth; cth = nth; nth = t;  t = ctl; ctl = ntl; ntl = t;
        }

        // join t-chain back to main
        cudaEventRecord(evT, s2);
        cudaStreamWaitEvent(0, evT, 0);

        // out-layer + coupling fused; then stats + bn/mu
        k_outcpl<<<MQ/8, 256>>>(csh, csl, cth, ctl,
                                s_w_out + (long)blk*HDIM*VV, s_b_out + (long)blk*VV,
                                t_w_out + (long)blk*HDIM*VV, t_b_out + (long)blk*VV, blk);
        k_stats<<<T2_*VV, 256>>>();
        k_bn_apply_mu<<<ceildiv(MQ, 256), 256>>>(bn_lg + (long)blk*VV, bn_bt + (long)blk*VV, blk);
    }

    // ---- final NLL ----
    k_final<<<ceildiv(BNN, 256), 256>>>((float*)d_out);
}